// round 8
// baseline (speedup 1.0000x reference)
#include <cuda_runtime.h>
#include <math.h>

#define NT 256
#define Tn 2048
#define Nn 256
#define Kn 64
#define MS 68            // padded row stride, multiple of 4 for float4

#define LSZ (Nn*MS)
#define MSZ (Kn*MS)
#define LOG2PI_F 1.8378770664093453f

// smem floats: Ls + 7 mats + 4 N-vec + midx + 5 K-vec + red + redu + sc + sint
#define SMEM_FLOATS (LSZ + 7*MSZ + 4*Nn + Nn + 5*Kn + Nn + Nn + 16 + 16)
#define SMEM_BYTES (SMEM_FLOATS * 4)

static __device__ __forceinline__ void nbar(int id, int cnt) {
    asm volatile("bar.sync %0, %1;" :: "r"(id), "r"(cnt) : "memory");
}

// ================= 64x64 GEMM helpers, 256 threads, 4x4 tiles ==============
// tr = tid>>4 (row tile), tc = tid&15 (col tile). Caller syncs.

// C = X * Y
static __device__ __forceinline__ void g_nn(int tid, float* __restrict__ C,
    const float* __restrict__ X, const float* __restrict__ Y)
{
    const int a = (tid >> 4) * 4, b = (tid & 15) * 4;
    float acc[4][4];
#pragma unroll
    for (int i = 0; i < 4; ++i)
#pragma unroll
        for (int j = 0; j < 4; ++j) acc[i][j] = 0.f;
#pragma unroll 4
    for (int k = 0; k < Kn; ++k) {
        float4 y4 = *reinterpret_cast<const float4*>(&Y[k * MS + b]);
        float xs[4];
#pragma unroll
        for (int i = 0; i < 4; ++i) xs[i] = X[(a + i) * MS + k];
#pragma unroll
        for (int i = 0; i < 4; ++i) {
            acc[i][0] += xs[i] * y4.x; acc[i][1] += xs[i] * y4.y;
            acc[i][2] += xs[i] * y4.z; acc[i][3] += xs[i] * y4.w;
        }
    }
#pragma unroll
    for (int i = 0; i < 4; ++i)
        *reinterpret_cast<float4*>(&C[(a + i) * MS + b]) =
            make_float4(acc[i][0], acc[i][1], acc[i][2], acc[i][3]);
}

// C = X * Y, scaled by s
static __device__ __forceinline__ void g_nn_scale(int tid, float* __restrict__ C,
    const float* __restrict__ X, const float* __restrict__ Y, float s)
{
    const int a = (tid >> 4) * 4, b = (tid & 15) * 4;
    float acc[4][4];
#pragma unroll
    for (int i = 0; i < 4; ++i)
#pragma unroll
        for (int j = 0; j < 4; ++j) acc[i][j] = 0.f;
#pragma unroll 4
    for (int k = 0; k < Kn; ++k) {
        float4 y4 = *reinterpret_cast<const float4*>(&Y[k * MS + b]);
        float xs[4];
#pragma unroll
        for (int i = 0; i < 4; ++i) xs[i] = X[(a + i) * MS + k];
#pragma unroll
        for (int i = 0; i < 4; ++i) {
            acc[i][0] += xs[i] * y4.x; acc[i][1] += xs[i] * y4.y;
            acc[i][2] += xs[i] * y4.z; acc[i][3] += xs[i] * y4.w;
        }
    }
#pragma unroll
    for (int i = 0; i < 4; ++i)
        *reinterpret_cast<float4*>(&C[(a + i) * MS + b]) =
            make_float4(s * acc[i][0], s * acc[i][1], s * acc[i][2], s * acc[i][3]);
}

// C = X^T * Y + I
static __device__ __forceinline__ void g_tn_I(int tid, float* __restrict__ C,
    const float* __restrict__ X, const float* __restrict__ Y)
{
    const int a = (tid >> 4) * 4, b = (tid & 15) * 4;
    float acc[4][4];
#pragma unroll
    for (int i = 0; i < 4; ++i)
#pragma unroll
        for (int j = 0; j < 4; ++j) acc[i][j] = 0.f;
#pragma unroll 4
    for (int k = 0; k < Kn; ++k) {
        float4 x4 = *reinterpret_cast<const float4*>(&X[k * MS + a]);
        float4 y4 = *reinterpret_cast<const float4*>(&Y[k * MS + b]);
        float xs[4] = {x4.x, x4.y, x4.z, x4.w};
#pragma unroll
        for (int i = 0; i < 4; ++i) {
            acc[i][0] += xs[i] * y4.x; acc[i][1] += xs[i] * y4.y;
            acc[i][2] += xs[i] * y4.z; acc[i][3] += xs[i] * y4.w;
        }
    }
#pragma unroll
    for (int i = 0; i < 4; ++i) {
#pragma unroll
        for (int j = 0; j < 4; ++j)
            if (a + i == b + j) acc[i][j] += 1.f;
        *reinterpret_cast<float4*>(&C[(a + i) * MS + b]) =
            make_float4(acc[i][0], acc[i][1], acc[i][2], acc[i][3]);
    }
}

// C = X * Y^T
static __device__ __forceinline__ void g_nt(int tid, float* __restrict__ C,
    const float* __restrict__ X, const float* __restrict__ Y)
{
    const int a = (tid >> 4) * 4, b = (tid & 15) * 4;
    float acc[4][4];
#pragma unroll
    for (int i = 0; i < 4; ++i)
#pragma unroll
        for (int j = 0; j < 4; ++j) acc[i][j] = 0.f;
#pragma unroll 4
    for (int k = 0; k < Kn; ++k) {
        float xs[4], ys[4];
#pragma unroll
        for (int i = 0; i < 4; ++i) xs[i] = X[(a + i) * MS + k];
#pragma unroll
        for (int j = 0; j < 4; ++j) ys[j] = Y[(b + j) * MS + k];
#pragma unroll
        for (int i = 0; i < 4; ++i)
#pragma unroll
            for (int j = 0; j < 4; ++j) acc[i][j] += xs[i] * ys[j];
    }
#pragma unroll
    for (int i = 0; i < 4; ++i)
        *reinterpret_cast<float4*>(&C[(a + i) * MS + b]) =
            make_float4(acc[i][0], acc[i][1], acc[i][2], acc[i][3]);
}

// C = X * Y^T + diag(dg)   (general-A Ppred)
static __device__ __forceinline__ void g_nt_diag(int tid, float* __restrict__ C,
    const float* __restrict__ X, const float* __restrict__ Y, const float* __restrict__ dg)
{
    const int a = (tid >> 4) * 4, b = (tid & 15) * 4;
    float acc[4][4];
#pragma unroll
    for (int i = 0; i < 4; ++i)
#pragma unroll
        for (int j = 0; j < 4; ++j) acc[i][j] = 0.f;
#pragma unroll 4
    for (int k = 0; k < Kn; ++k) {
        float xs[4], ys[4];
#pragma unroll
        for (int i = 0; i < 4; ++i) xs[i] = X[(a + i) * MS + k];
#pragma unroll
        for (int j = 0; j < 4; ++j) ys[j] = Y[(b + j) * MS + k];
#pragma unroll
        for (int i = 0; i < 4; ++i)
#pragma unroll
            for (int j = 0; j < 4; ++j) acc[i][j] += xs[i] * ys[j];
    }
#pragma unroll
    for (int i = 0; i < 4; ++i) {
#pragma unroll
        for (int j = 0; j < 4; ++j)
            if (a + i == b + j) acc[i][j] += dg[a + i];
        *reinterpret_cast<float4*>(&C[(a + i) * MS + b]) =
            make_float4(acc[i][0], acc[i][1], acc[i][2], acc[i][3]);
    }
}

// C = Y - X*Y   (T2 = (I-KGL)*Ppred)
static __device__ __forceinline__ void g_nn_rsub(int tid, float* __restrict__ C,
    const float* __restrict__ X, const float* __restrict__ Y)
{
    const int a = (tid >> 4) * 4, b = (tid & 15) * 4;
    float acc[4][4];
#pragma unroll
    for (int i = 0; i < 4; ++i)
#pragma unroll
        for (int j = 0; j < 4; ++j) acc[i][j] = 0.f;
#pragma unroll 4
    for (int k = 0; k < Kn; ++k) {
        float4 y4 = *reinterpret_cast<const float4*>(&Y[k * MS + b]);
        float xs[4];
#pragma unroll
        for (int i = 0; i < 4; ++i) xs[i] = X[(a + i) * MS + k];
#pragma unroll
        for (int i = 0; i < 4; ++i) {
            acc[i][0] += xs[i] * y4.x; acc[i][1] += xs[i] * y4.y;
            acc[i][2] += xs[i] * y4.z; acc[i][3] += xs[i] * y4.w;
        }
    }
#pragma unroll
    for (int i = 0; i < 4; ++i) {
        float4 yy = *reinterpret_cast<const float4*>(&Y[(a + i) * MS + b]);
        *reinterpret_cast<float4*>(&C[(a + i) * MS + b]) =
            make_float4(yy.x - acc[i][0], yy.y - acc[i][1],
                        yy.z - acc[i][2], yy.w - acc[i][3]);
    }
}

// C = X + A2 - X*Y^T   (Pnew = T2 + KGRKG - T2*KGL^T)
static __device__ __forceinline__ void g_joseph(int tid, float* __restrict__ C,
    const float* __restrict__ X, const float* __restrict__ Y, const float* __restrict__ A2)
{
    const int a = (tid >> 4) * 4, b = (tid & 15) * 4;
    float acc[4][4];
#pragma unroll
    for (int i = 0; i < 4; ++i)
#pragma unroll
        for (int j = 0; j < 4; ++j) acc[i][j] = 0.f;
#pragma unroll 4
    for (int k = 0; k < Kn; ++k) {
        float xs[4], ys[4];
#pragma unroll
        for (int i = 0; i < 4; ++i) xs[i] = X[(a + i) * MS + k];
#pragma unroll
        for (int j = 0; j < 4; ++j) ys[j] = Y[(b + j) * MS + k];
#pragma unroll
        for (int i = 0; i < 4; ++i)
#pragma unroll
            for (int j = 0; j < 4; ++j) acc[i][j] += xs[i] * ys[j];
    }
#pragma unroll
    for (int i = 0; i < 4; ++i) {
        float4 xx = *reinterpret_cast<const float4*>(&X[(a + i) * MS + b]);
        float4 aa = *reinterpret_cast<const float4*>(&A2[(a + i) * MS + b]);
        *reinterpret_cast<float4*>(&C[(a + i) * MS + b]) =
            make_float4(xx.x + aa.x - acc[i][0], xx.y + aa.y - acc[i][1],
                        xx.z + aa.z - acc[i][2], xx.w + aa.w - acc[i][3]);
    }
}

// ===== single-warp lower Cholesky (warp 0 only); returns 2*sum(log diag) on
// lane 0 (undefined on other lanes). In place; touches lower+diag only.
static __device__ float chol_warp(float* __restrict__ A)
{
    const int l = threadIdx.x & 31;
    float lds = 0.f;
    for (int j = 0; j < Kn; ++j) {
        float dj = 0.f;
        if (l == 0) {
            dj = sqrtf(A[j * MS + j]);
            A[j * MS + j] = dj;
            lds += logf(dj);
        }
        dj = __shfl_sync(0xffffffffu, dj, 0);
        float inv = 1.f / dj;
        for (int i = j + 1 + l; i < Kn; i += 32) A[i * MS + j] *= inv;
        __syncwarp();
        for (int r = j + 1 + l; r < Kn; r += 32) {
            float arj = A[r * MS + j];
            for (int c = j + 1; c <= r; ++c)
                A[r * MS + c] -= arj * A[c * MS + j];
        }
        __syncwarp();
    }
    return 2.f * lds;
}

// ===== barrier-free triangular inverse: thread j (j<64) solves column j of
// X = H^{-1} (forward substitution); upper of X zeroed. Threads 0..63 only.
static __device__ void colsolve(int j, const float* __restrict__ H, float* __restrict__ X)
{
    for (int i = 0; i < j; ++i) X[i * MS + j] = 0.f;
    for (int i = j; i < Kn; ++i) {
        float s = (i == j) ? 1.f : 0.f;
        for (int k = j; k < i; ++k) s -= H[i * MS + k] * X[k * MS + j];
        X[i * MS + j] = s / H[i * MS + i];
    }
}

// ===========================================================================

__global__ __launch_bounds__(NT, 1)
void kf_kernel(const float* __restrict__ obs, const float* __restrict__ Lam,
               const float* __restrict__ Araw, const float* __restrict__ logQ,
               const float* __restrict__ logR, float* __restrict__ out)
{
    extern __shared__ float sm[];
    float* Ls  = sm;                 // [Nn][MS]
    float* Pm  = Ls + LSZ;           // P (persistent)
    float* B1  = Pm + MSZ;           // G / KGL
    float* B2  = B1 + MSZ;           // Ppred
    float* B3  = B2 + MSZ;           // Wm / Ttmp
    float* B4  = B3 + MSZ;           // W2 / Wr / KGRKG
    float* B5  = B4 + MSZ;           // Wfull / Y / H / E / T2
    float* B6  = B5 + MSZ;           // WG / Hinv / Minv / Pnew / scratch
    float* wv   = B6 + MSZ;          // v/d
    float* wmv  = wv + Nn;           // m/d
    float* w2v  = wmv + Nn;          // m/d^2
    float* dinv = w2v + Nn;          // 1/d
    int*   midx = (int*)(dinv + Nn);
    float* zv  = (float*)(midx + Nn);
    float* zpv = zv + Kn;
    float* uv  = zpv + Kn;
    float* xv  = uv + Kn;
    float* qd  = xv + Kn;
    float* red  = qd + Kn;           // [Nn] sdv terms / prologue scratch
    float* redu = red + Nn;          // [Nn] u partials
    float* sc   = redu + Nn;         // 16 scalars
    int*   sint = (int*)(sc + 16);   // 16 ints

    const int tid  = threadIdx.x;
    const int warp = tid >> 5;
    const int lane = tid & 31;

    // ------------------------------ prologue ------------------------------
    for (int e = tid; e < Kn * Kn; e += NT)
        B1[(e >> 6) * MS + (e & 63)] = Araw[e];
    if (tid < Kn) qd[tid] = expf(logQ[tid]);
    {   // tid indexes all Nn channels (NT == Nn)
        float r = expf(logR[tid]);
        dinv[tid] = 1.f / (r + 1e-4f);
    }
    if (tid == 0) { sint[1] = 1; }
    __syncthreads();
    if (tid == 0) {
        float ld = 0.f;
        for (int i = 0; i < Nn; ++i) ld += logf(1.f / dinv[i]);
        sc[0] = ld;                          // logdet(D) per step
        int u = 1;
        for (int i = 1; i < Nn; ++i) if (dinv[i] != dinv[0]) u = 0;
        sint[2] = u;                         // uniform-R flag
        sc[8] = 1.f - 1e-4f * dinv[0];       // Wr scale when uniform R
    }
    {   // exact scalar-A detection
        float a00 = Araw[0];
        int ok = 1;
        for (int e = tid; e < Kn * Kn; e += NT) {
            int r = e >> 6, c = e & 63;
            float v = Araw[e];
            if (r == c) { if (v != a00) ok = 0; }
            else        { if (v != 0.f) ok = 0; }
        }
        if (!ok) atomicAnd(&sint[1], 0);
    }
    // power iteration for sigma_max(A_raw)
    if (tid < Kn) red[tid] = 1.f;
    __syncthreads();
#pragma unroll 1
    for (int it = 0; it < 64; ++it) {
        if (tid < Kn) {
            float s = 0.f;
            for (int k = 0; k < Kn; ++k) s += B1[tid * MS + k] * red[k];
            redu[tid] = s;
        }
        __syncthreads();
        if (tid < Kn) {
            float s = 0.f;
            for (int k = 0; k < Kn; ++k) s += B1[k * MS + tid] * redu[k];
            redu[64 + tid] = s;
        }
        __syncthreads();
        if (tid == 0) {
            float n = 0.f;
            for (int i = 0; i < Kn; ++i) n += redu[64 + i] * redu[64 + i];
            sc[1] = rsqrtf(fmaxf(n, 1e-30f));
        }
        __syncthreads();
        if (tid < Kn) red[tid] = redu[64 + tid] * sc[1];
        __syncthreads();
    }
    if (tid < Kn) {
        float s = 0.f;
        for (int k = 0; k < Kn; ++k) s += B1[tid * MS + k] * red[k];
        redu[tid] = s;
    }
    __syncthreads();
    if (tid == 0) {
        float n = 0.f;
        for (int i = 0; i < Kn; ++i) n += redu[i] * redu[i];
        float sigma = sqrtf(n);
        sc[2] = 0.98f / (sigma + 1e-6f);     // A scale
        sc[6] = sc[2] * Araw[0];             // scalar a (if diagonal)
    }
    // init P = I, z = 0; load Ls(0)
    for (int e = tid; e < Kn * Kn; e += NT) {
        int r = e >> 6, c = e & 63;
        Pm[r * MS + c] = (r == c) ? 1.f : 0.f;
    }
    if (tid < Kn) zv[tid] = 0.f;
    {
        const float4* Lg = (const float4*)Lam;
        for (int e4 = tid; e4 < (Nn * Kn) / 4; e4 += NT) {
            float4 v4 = Lg[e4];
            int i = e4 >> 4, c = (e4 & 15) << 2;
            *reinterpret_cast<float4*>(&Ls[i * MS + c]) = v4;
        }
    }
    __syncthreads();
    const int   scA   = sint[1];
    const int   unifR = sint[2];
    const float aA    = sc[6];
    const float ldD   = sc[0];
    const float crS   = sc[8];
    const float ascale = sc[2];

    // ------------------------------ main loop ------------------------------
#pragma unroll 1
    for (int t = 0; t < Tn; ++t) {
        // ---- A: Ppred -> B2 (full) and B1 (lower, zero upper); zpv ----
        if (scA) {
            float a2 = aA * aA;
            for (int e = tid; e < Kn * Kn; e += NT) {
                int a = e >> 6, b = e & 63;
                float v = a2 * Pm[a * MS + b];
                if (a == b) v += qd[a];
                B2[a * MS + b] = v;
                B1[a * MS + b] = (b <= a) ? v : 0.f;
            }
            if (tid < Kn) zpv[tid] = aA * zv[tid];
            __syncthreads();
        } else {
            for (int e = tid; e < Kn * Kn; e += NT)
                B6[(e >> 6) * MS + (e & 63)] = ascale * Araw[e];
            __syncthreads();
            g_nn(tid, B5, B6, Pm);                // B5 = A*P
            if (tid < Kn) {
                float s = 0.f;
                for (int k = 0; k < Kn; ++k) s += B6[tid * MS + k] * zv[k];
                zpv[tid] = s;
            }
            __syncthreads();
            g_nt_diag(tid, B2, B5, B6, qd);       // B2 = (A P)A^T + Q
            __syncthreads();
            for (int e = tid; e < Kn * Kn; e += NT) {
                int a = e >> 6, b = e & 63;
                B1[a * MS + b] = (b <= a) ? B2[a * MS + b] : 0.f;
            }
            __syncthreads();
        }

        // ---- B: innovation + weights (thread == channel) ----
        bool nanflag;
        {
            float y = obs[(size_t)t * Nn + tid];
            float yp = 0.f;
#pragma unroll 8
            for (int a = 0; a < Kn; ++a) yp += Ls[tid * MS + a] * zpv[a];
            nanflag = !(y == y);
            float vi = nanflag ? 0.f : (y - yp);
            float di = dinv[tid];
            wv[tid]  = vi * di;
            wmv[tid] = nanflag ? 0.f : di;
            w2v[tid] = nanflag ? 0.f : di * di;
            red[tid] = vi * vi * di;           // sdv terms
            unsigned bal = __ballot_sync(0xffffffffu, nanflag);
            if (lane == 0) sint[8 + warp] = (int)bal;
        }
        __syncthreads();

        // ---- C: u partials + masked-index compaction ----
        {
            int a = tid & 63, s4 = tid >> 6;
            float part = 0.f;
#pragma unroll 8
            for (int ii = 0; ii < 64; ++ii) {
                int i = s4 * 64 + ii;
                part += Ls[i * MS + a] * wv[i];
            }
            redu[tid] = part;
        }
        if (nanflag) {
            int base = 0;
            for (int k = 0; k < warp; ++k) base += __popc((unsigned)sint[8 + k]);
            base += __popc(((unsigned)sint[8 + warp]) & ((1u << lane) - 1u));
            midx[base] = tid;
        }
        if (tid == 0) {
            int nm = 0;
            for (int k = 0; k < 8; ++k) nm += __popc((unsigned)sint[8 + k]);
            sint[0] = nm;
            sc[3] = (float)(Nn - nm);
        }
        __syncthreads();
        const int nm = sint[0];

        // ---- D: warp0 chol(Ppred)=G  ||  warps1-7: u, SYRK, Wfull/Wr ----
        if (warp == 0) {
            // sdv = sum red (fixed order), then Cholesky
            float s = 0.f;
            for (int i = lane; i < Nn; i += 32) s += red[i];
#pragma unroll
            for (int o = 16; o > 0; o >>= 1) s += __shfl_down_sync(0xffffffffu, s, o);
            if (lane == 0) sc[4] = s;
            chol_warp(B1);                        // B1 = G (lower), upper stays 0
        } else {
            if (tid < 32 + Kn) {
                int a = tid - 32;
                uv[a] = redu[a] + redu[64 + a] + redu[128 + a] + redu[192 + a];
            }
            // lower-triangle 4x4 tiles of Wm (and W2 if non-uniform R)
            int tl = tid - 32;
            if (tl < 136) {
                int ti = 0;
                while (((ti + 1) * (ti + 2)) / 2 <= tl) ++ti;
                int tj = tl - (ti * (ti + 1)) / 2;
                int a = 4 * ti, b = 4 * tj;
                float m[4][4], q[4][4];
#pragma unroll
                for (int i = 0; i < 4; ++i)
#pragma unroll
                    for (int j = 0; j < 4; ++j) { m[i][j] = 0.f; q[i][j] = 0.f; }
                if (unifR) {
#pragma unroll 2
                    for (int i = 0; i < Nn; ++i) {
                        float cm = wmv[i];
                        float4 la = *reinterpret_cast<const float4*>(&Ls[i * MS + a]);
                        float4 lb = *reinterpret_cast<const float4*>(&Ls[i * MS + b]);
                        float law[4] = {cm * la.x, cm * la.y, cm * la.z, cm * la.w};
                        float lbv[4] = {lb.x, lb.y, lb.z, lb.w};
#pragma unroll
                        for (int ii = 0; ii < 4; ++ii)
#pragma unroll
                            for (int jj = 0; jj < 4; ++jj) m[ii][jj] += law[ii] * lbv[jj];
                    }
                } else {
#pragma unroll 2
                    for (int i = 0; i < Nn; ++i) {
                        float cm = wmv[i];
                        float4 la = *reinterpret_cast<const float4*>(&Ls[i * MS + a]);
                        float4 lb = *reinterpret_cast<const float4*>(&Ls[i * MS + b]);
                        float law[4] = {cm * la.x, cm * la.y, cm * la.z, cm * la.w};
                        float lbw[4] = {cm * lb.x, cm * lb.y, cm * lb.z, cm * lb.w};
                        float lbv[4] = {lb.x, lb.y, lb.z, lb.w};
#pragma unroll
                        for (int ii = 0; ii < 4; ++ii)
#pragma unroll
                            for (int jj = 0; jj < 4; ++jj) {
                                m[ii][jj] += law[ii] * lbv[jj];
                                q[ii][jj] += law[ii] * lbw[jj];  // m/d^2 weights
                            }
                    }
                }
#pragma unroll
                for (int ii = 0; ii < 4; ++ii)
#pragma unroll
                    for (int jj = 0; jj < 4; ++jj) {
                        B3[(a + ii) * MS + (b + jj)] = m[ii][jj];
                        if (!unifR) B4[(a + ii) * MS + (b + jj)] = q[ii][jj];
                    }
            }
            nbar(1, 224);
            // mirror + Wfull (B5) + Wr (B4) over lower triangle
            for (int e = tid - 32; e < Kn * Kn; e += (NT - 32)) {
                int a = e >> 6, b = e & 63;
                if (b > a) continue;
                float wm = B3[a * MS + b];
                float wr = unifR ? (crS * wm) : (wm - 1e-4f * B4[a * MS + b]);
                float wf = wm;
                for (int j = 0; j < nm; ++j) {
                    int ich = midx[j];
                    wf += dinv[ich] * Ls[ich * MS + a] * Ls[ich * MS + b];
                }
                B3[b * MS + a] = wm;
                B4[a * MS + b] = wr; B4[b * MS + a] = wr;
                B5[a * MS + b] = wf; B5[b * MS + a] = wf;
            }
        }
        __syncthreads();

        // ---- E1: WG = Wfull * G ----
        g_nn(tid, B6, B5, B1);
        __syncthreads();
        // ---- E2: Y + I = G^T * WG + I ----
        g_tn_I(tid, B5, B1, B6);
        __syncthreads();

        // ---- F: warp0 chol(Y+I)=H (logdet) || tids 64+ prefetch L(t+1) ----
        if (warp == 0) {
            float ld = chol_warp(B5);            // B5 lower = H
            if (lane == 0) sc[5] = ld;           // = logdetP + logdetM
        } else if (tid >= 64 && (t + 1) < Tn) {
            const float4* Lg = (const float4*)(Lam + (size_t)(t + 1) * Nn * Kn);
            for (int e4 = tid - 64; e4 < (Nn * Kn) / 4; e4 += (NT - 64)) {
                float4 v4 = Lg[e4];
                int i = e4 >> 4, c = (e4 & 15) << 2;
                *reinterpret_cast<float4*>(&Ls[i * MS + c]) = v4;
            }
        }
        __syncthreads();

        // ---- G: Hinv = H^{-1} by independent columns (tids 0..63) ----
        if (tid < Kn) colsolve(tid, B5, B6);
        __syncthreads();

        // ---- H1: E = G * Hinv^T ----
        g_nt(tid, B5, B1, B6);
        __syncthreads();
        // ---- H2: Minv = E * E^T ----
        g_nt(tid, B6, B5, B5);
        __syncthreads();

        // ---- I: x = Minv * u ----
        if (tid < Kn) {
            float s = 0.f;
#pragma unroll 8
            for (int k = 0; k < Kn; ++k) s += B6[tid * MS + k] * uv[k];
            xv[tid] = s;
        }
        __syncthreads();

        // ---- J: KGL = Minv * Wm ----
        g_nn(tid, B1, B6, B3);
        __syncthreads();

        // ---- K/L: KGRKG -> B4 ; tid0 computes quad ----
        if (tid == 0) {
            float q = 0.f;
            for (int i = 0; i < Kn; ++i) q += uv[i] * xv[i];
            sc[7] = q;
        }
        if (unifR) {
            // KGRKG = crS * KGL * Minv
            g_nn_scale(tid, B4, B1, B6, crS);
            __syncthreads();
        } else {
            g_nn(tid, B3, B6, B4);               // Ttmp = Minv*Wr (Wm dead)
            __syncthreads();
            g_nn(tid, B4, B3, B6);               // KGRKG = Ttmp*Minv
            __syncthreads();
        }

        // ---- M: T2 = Ppred - KGL*Ppred ----
        g_nn_rsub(tid, B5, B1, B2);
        __syncthreads();
        // ---- N: Pnew = T2 + KGRKG - T2*KGL^T ----
        g_joseph(tid, B6, B5, B1, B4);
        __syncthreads();

        // ---- O: symmetrize P; outputs ----
        for (int e = tid; e < Kn * Kn; e += NT) {
            int a = e >> 6, b = e & 63;
            Pm[a * MS + b] = 0.5f * (B6[a * MS + b] + B6[b * MS + a]);
        }
        if (tid < Kn) {
            float z = zpv[tid] + xv[tid];
            zv[tid] = z;
            out[(size_t)t * (Kn + 1) + tid] = z;
        }
        if (tid == 0) {
            float mahal = sc[4] - sc[7];
            float ll = -0.5f * (sc[3] * LOG2PI_F + ldD + sc[5] + mahal);
            if (!(ll == ll)) ll = -1e6f;
            out[(size_t)t * (Kn + 1) + Kn] = ll;
        }
        __syncthreads();
    }
}

extern "C" void kernel_launch(void* const* d_in, const int* in_sizes, int n_in,
                              void* d_out, int out_size)
{
    const float* obs  = (const float*)d_in[0];
    const float* Lam  = (const float*)d_in[1];
    const float* Araw = (const float*)d_in[2];
    const float* lQ   = (const float*)d_in[3];
    const float* lR   = (const float*)d_in[4];
    float* out = (float*)d_out;

    cudaFuncSetAttribute(kf_kernel, cudaFuncAttributeMaxDynamicSharedMemorySize,
                         SMEM_BYTES);
    kf_kernel<<<1, NT, SMEM_BYTES>>>(obs, Lam, Araw, lQ, lR, out);
}

// round 9
// speedup vs baseline: 1.0016x; 1.0016x over previous
#include <cuda_runtime.h>
#include <math.h>

#define NT 256
#define Tn 2048
#define Nn 256
#define Kn 64
#define MS 68            // padded row stride, multiple of 4 for float4

#define LSZ (Nn*MS)
#define MSZ (Kn*MS)
#define LOG2PI_F 1.8378770664093453f

// smem floats: Ls + 7 mats + 4 N-vec + midx + 5 K-vec + red + redu + sc + sint
#define SMEM_FLOATS (LSZ + 7*MSZ + 4*Nn + Nn + 5*Kn + Nn + Nn + 16 + 16)
#define SMEM_BYTES (SMEM_FLOATS * 4)

static __device__ __forceinline__ void nbar(int id, int cnt) {
    asm volatile("bar.sync %0, %1;" :: "r"(id), "r"(cnt) : "memory");
}

// ================= 64x64 GEMM helpers, 256 threads, 4x4 tiles ==============
// tr = tid>>4 (row tile), tc = tid&15 (col tile). Caller syncs.

// C = X * Y
static __device__ __forceinline__ void g_nn(int tid, float* __restrict__ C,
    const float* __restrict__ X, const float* __restrict__ Y)
{
    const int a = (tid >> 4) * 4, b = (tid & 15) * 4;
    float acc[4][4];
#pragma unroll
    for (int i = 0; i < 4; ++i)
#pragma unroll
        for (int j = 0; j < 4; ++j) acc[i][j] = 0.f;
#pragma unroll 4
    for (int k = 0; k < Kn; ++k) {
        float4 y4 = *reinterpret_cast<const float4*>(&Y[k * MS + b]);
        float xs[4];
#pragma unroll
        for (int i = 0; i < 4; ++i) xs[i] = X[(a + i) * MS + k];
#pragma unroll
        for (int i = 0; i < 4; ++i) {
            acc[i][0] += xs[i] * y4.x; acc[i][1] += xs[i] * y4.y;
            acc[i][2] += xs[i] * y4.z; acc[i][3] += xs[i] * y4.w;
        }
    }
#pragma unroll
    for (int i = 0; i < 4; ++i)
        *reinterpret_cast<float4*>(&C[(a + i) * MS + b]) =
            make_float4(acc[i][0], acc[i][1], acc[i][2], acc[i][3]);
}

// C = X * Y, scaled by s
static __device__ __forceinline__ void g_nn_scale(int tid, float* __restrict__ C,
    const float* __restrict__ X, const float* __restrict__ Y, float s)
{
    const int a = (tid >> 4) * 4, b = (tid & 15) * 4;
    float acc[4][4];
#pragma unroll
    for (int i = 0; i < 4; ++i)
#pragma unroll
        for (int j = 0; j < 4; ++j) acc[i][j] = 0.f;
#pragma unroll 4
    for (int k = 0; k < Kn; ++k) {
        float4 y4 = *reinterpret_cast<const float4*>(&Y[k * MS + b]);
        float xs[4];
#pragma unroll
        for (int i = 0; i < 4; ++i) xs[i] = X[(a + i) * MS + k];
#pragma unroll
        for (int i = 0; i < 4; ++i) {
            acc[i][0] += xs[i] * y4.x; acc[i][1] += xs[i] * y4.y;
            acc[i][2] += xs[i] * y4.z; acc[i][3] += xs[i] * y4.w;
        }
    }
#pragma unroll
    for (int i = 0; i < 4; ++i)
        *reinterpret_cast<float4*>(&C[(a + i) * MS + b]) =
            make_float4(s * acc[i][0], s * acc[i][1], s * acc[i][2], s * acc[i][3]);
}

// C = X^T * Y + I
static __device__ __forceinline__ void g_tn_I(int tid, float* __restrict__ C,
    const float* __restrict__ X, const float* __restrict__ Y)
{
    const int a = (tid >> 4) * 4, b = (tid & 15) * 4;
    float acc[4][4];
#pragma unroll
    for (int i = 0; i < 4; ++i)
#pragma unroll
        for (int j = 0; j < 4; ++j) acc[i][j] = 0.f;
#pragma unroll 4
    for (int k = 0; k < Kn; ++k) {
        float4 x4 = *reinterpret_cast<const float4*>(&X[k * MS + a]);
        float4 y4 = *reinterpret_cast<const float4*>(&Y[k * MS + b]);
        float xs[4] = {x4.x, x4.y, x4.z, x4.w};
#pragma unroll
        for (int i = 0; i < 4; ++i) {
            acc[i][0] += xs[i] * y4.x; acc[i][1] += xs[i] * y4.y;
            acc[i][2] += xs[i] * y4.z; acc[i][3] += xs[i] * y4.w;
        }
    }
#pragma unroll
    for (int i = 0; i < 4; ++i) {
#pragma unroll
        for (int j = 0; j < 4; ++j)
            if (a + i == b + j) acc[i][j] += 1.f;
        *reinterpret_cast<float4*>(&C[(a + i) * MS + b]) =
            make_float4(acc[i][0], acc[i][1], acc[i][2], acc[i][3]);
    }
}

// C = X * Y^T
static __device__ __forceinline__ void g_nt(int tid, float* __restrict__ C,
    const float* __restrict__ X, const float* __restrict__ Y)
{
    const int a = (tid >> 4) * 4, b = (tid & 15) * 4;
    float acc[4][4];
#pragma unroll
    for (int i = 0; i < 4; ++i)
#pragma unroll
        for (int j = 0; j < 4; ++j) acc[i][j] = 0.f;
#pragma unroll 4
    for (int k = 0; k < Kn; ++k) {
        float xs[4], ys[4];
#pragma unroll
        for (int i = 0; i < 4; ++i) xs[i] = X[(a + i) * MS + k];
#pragma unroll
        for (int j = 0; j < 4; ++j) ys[j] = Y[(b + j) * MS + k];
#pragma unroll
        for (int i = 0; i < 4; ++i)
#pragma unroll
            for (int j = 0; j < 4; ++j) acc[i][j] += xs[i] * ys[j];
    }
#pragma unroll
    for (int i = 0; i < 4; ++i)
        *reinterpret_cast<float4*>(&C[(a + i) * MS + b]) =
            make_float4(acc[i][0], acc[i][1], acc[i][2], acc[i][3]);
}

// C = X * Y^T + diag(dg)   (general-A Ppred)
static __device__ __forceinline__ void g_nt_diag(int tid, float* __restrict__ C,
    const float* __restrict__ X, const float* __restrict__ Y, const float* __restrict__ dg)
{
    const int a = (tid >> 4) * 4, b = (tid & 15) * 4;
    float acc[4][4];
#pragma unroll
    for (int i = 0; i < 4; ++i)
#pragma unroll
        for (int j = 0; j < 4; ++j) acc[i][j] = 0.f;
#pragma unroll 4
    for (int k = 0; k < Kn; ++k) {
        float xs[4], ys[4];
#pragma unroll
        for (int i = 0; i < 4; ++i) xs[i] = X[(a + i) * MS + k];
#pragma unroll
        for (int j = 0; j < 4; ++j) ys[j] = Y[(b + j) * MS + k];
#pragma unroll
        for (int i = 0; i < 4; ++i)
#pragma unroll
            for (int j = 0; j < 4; ++j) acc[i][j] += xs[i] * ys[j];
    }
#pragma unroll
    for (int i = 0; i < 4; ++i) {
#pragma unroll
        for (int j = 0; j < 4; ++j)
            if (a + i == b + j) acc[i][j] += dg[a + i];
        *reinterpret_cast<float4*>(&C[(a + i) * MS + b]) =
            make_float4(acc[i][0], acc[i][1], acc[i][2], acc[i][3]);
    }
}

// C = Y - X*Y   (T2 = (I-KGL)*Ppred)
static __device__ __forceinline__ void g_nn_rsub(int tid, float* __restrict__ C,
    const float* __restrict__ X, const float* __restrict__ Y)
{
    const int a = (tid >> 4) * 4, b = (tid & 15) * 4;
    float acc[4][4];
#pragma unroll
    for (int i = 0; i < 4; ++i)
#pragma unroll
        for (int j = 0; j < 4; ++j) acc[i][j] = 0.f;
#pragma unroll 4
    for (int k = 0; k < Kn; ++k) {
        float4 y4 = *reinterpret_cast<const float4*>(&Y[k * MS + b]);
        float xs[4];
#pragma unroll
        for (int i = 0; i < 4; ++i) xs[i] = X[(a + i) * MS + k];
#pragma unroll
        for (int i = 0; i < 4; ++i) {
            acc[i][0] += xs[i] * y4.x; acc[i][1] += xs[i] * y4.y;
            acc[i][2] += xs[i] * y4.z; acc[i][3] += xs[i] * y4.w;
        }
    }
#pragma unroll
    for (int i = 0; i < 4; ++i) {
        float4 yy = *reinterpret_cast<const float4*>(&Y[(a + i) * MS + b]);
        *reinterpret_cast<float4*>(&C[(a + i) * MS + b]) =
            make_float4(yy.x - acc[i][0], yy.y - acc[i][1],
                        yy.z - acc[i][2], yy.w - acc[i][3]);
    }
}

// C = X + A2 - X*Y^T   (Pnew = T2 + KGRKG - T2*KGL^T)
static __device__ __forceinline__ void g_joseph(int tid, float* __restrict__ C,
    const float* __restrict__ X, const float* __restrict__ Y, const float* __restrict__ A2)
{
    const int a = (tid >> 4) * 4, b = (tid & 15) * 4;
    float acc[4][4];
#pragma unroll
    for (int i = 0; i < 4; ++i)
#pragma unroll
        for (int j = 0; j < 4; ++j) acc[i][j] = 0.f;
#pragma unroll 4
    for (int k = 0; k < Kn; ++k) {
        float xs[4], ys[4];
#pragma unroll
        for (int i = 0; i < 4; ++i) xs[i] = X[(a + i) * MS + k];
#pragma unroll
        for (int j = 0; j < 4; ++j) ys[j] = Y[(b + j) * MS + k];
#pragma unroll
        for (int i = 0; i < 4; ++i)
#pragma unroll
            for (int j = 0; j < 4; ++j) acc[i][j] += xs[i] * ys[j];
    }
#pragma unroll
    for (int i = 0; i < 4; ++i) {
        float4 xx = *reinterpret_cast<const float4*>(&X[(a + i) * MS + b]);
        float4 aa = *reinterpret_cast<const float4*>(&A2[(a + i) * MS + b]);
        *reinterpret_cast<float4*>(&C[(a + i) * MS + b]) =
            make_float4(xx.x + aa.x - acc[i][0], xx.y + aa.y - acc[i][1],
                        xx.z + aa.z - acc[i][2], xx.w + aa.w - acc[i][3]);
    }
}

// ===== single-warp lower Cholesky (warp 0 only); returns 2*sum(log diag) on
// lane 0 (undefined on other lanes). In place; touches lower+diag only.
static __device__ float chol_warp(float* __restrict__ A)
{
    const int l = threadIdx.x & 31;
    float lds = 0.f;
    for (int j = 0; j < Kn; ++j) {
        float dj = 0.f;
        if (l == 0) {
            dj = sqrtf(A[j * MS + j]);
            A[j * MS + j] = dj;
            lds += logf(dj);
        }
        dj = __shfl_sync(0xffffffffu, dj, 0);
        float inv = 1.f / dj;
        for (int i = j + 1 + l; i < Kn; i += 32) A[i * MS + j] *= inv;
        __syncwarp();
        for (int r = j + 1 + l; r < Kn; r += 32) {
            float arj = A[r * MS + j];
            for (int c = j + 1; c <= r; ++c)
                A[r * MS + c] -= arj * A[c * MS + j];
        }
        __syncwarp();
    }
    return 2.f * lds;
}

// ===== barrier-free triangular inverse: thread j (j<64) solves column j of
// X = H^{-1} (forward substitution); upper of X zeroed. Threads 0..63 only.
static __device__ void colsolve(int j, const float* __restrict__ H, float* __restrict__ X)
{
    for (int i = 0; i < j; ++i) X[i * MS + j] = 0.f;
    for (int i = j; i < Kn; ++i) {
        float s = (i == j) ? 1.f : 0.f;
        for (int k = j; k < i; ++k) s -= H[i * MS + k] * X[k * MS + j];
        X[i * MS + j] = s / H[i * MS + i];
    }
}

// ===========================================================================

__global__ __launch_bounds__(NT, 1)
void kf_kernel(const float* __restrict__ obs, const float* __restrict__ Lam,
               const float* __restrict__ Araw, const float* __restrict__ logQ,
               const float* __restrict__ logR, float* __restrict__ out)
{
    extern __shared__ float sm[];
    float* Ls  = sm;                 // [Nn][MS]
    float* Pm  = Ls + LSZ;           // P (persistent)
    float* B1  = Pm + MSZ;           // G / KGL
    float* B2  = B1 + MSZ;           // Ppred
    float* B3  = B2 + MSZ;           // Wm / Ttmp
    float* B4  = B3 + MSZ;           // W2 / Wr / KGRKG
    float* B5  = B4 + MSZ;           // Wfull / Y / H / E / T2
    float* B6  = B5 + MSZ;           // WG / Hinv / Minv / Pnew / scratch
    float* wv   = B6 + MSZ;          // v/d
    float* wmv  = wv + Nn;           // m/d
    float* w2v  = wmv + Nn;          // m/d^2
    float* dinv = w2v + Nn;          // 1/d
    int*   midx = (int*)(dinv + Nn);
    float* zv  = (float*)(midx + Nn);
    float* zpv = zv + Kn;
    float* uv  = zpv + Kn;
    float* xv  = uv + Kn;
    float* qd  = xv + Kn;
    float* red  = qd + Kn;           // [Nn] sdv terms / prologue scratch
    float* redu = red + Nn;          // [Nn] u partials
    float* sc   = redu + Nn;         // 16 scalars
    int*   sint = (int*)(sc + 16);   // 16 ints

    const int tid  = threadIdx.x;
    const int warp = tid >> 5;
    const int lane = tid & 31;

    // ------------------------------ prologue ------------------------------
    for (int e = tid; e < Kn * Kn; e += NT)
        B1[(e >> 6) * MS + (e & 63)] = Araw[e];
    if (tid < Kn) qd[tid] = expf(logQ[tid]);
    {   // tid indexes all Nn channels (NT == Nn)
        float r = expf(logR[tid]);
        dinv[tid] = 1.f / (r + 1e-4f);
    }
    if (tid == 0) { sint[1] = 1; }
    __syncthreads();
    if (tid == 0) {
        float ld = 0.f;
        for (int i = 0; i < Nn; ++i) ld += logf(1.f / dinv[i]);
        sc[0] = ld;                          // logdet(D) per step
        int u = 1;
        for (int i = 1; i < Nn; ++i) if (dinv[i] != dinv[0]) u = 0;
        sint[2] = u;                         // uniform-R flag
        sc[8] = 1.f - 1e-4f * dinv[0];       // Wr scale when uniform R
    }
    {   // exact scalar-A detection
        float a00 = Araw[0];
        int ok = 1;
        for (int e = tid; e < Kn * Kn; e += NT) {
            int r = e >> 6, c = e & 63;
            float v = Araw[e];
            if (r == c) { if (v != a00) ok = 0; }
            else        { if (v != 0.f) ok = 0; }
        }
        if (!ok) atomicAnd(&sint[1], 0);
    }
    // power iteration for sigma_max(A_raw)
    if (tid < Kn) red[tid] = 1.f;
    __syncthreads();
#pragma unroll 1
    for (int it = 0; it < 64; ++it) {
        if (tid < Kn) {
            float s = 0.f;
            for (int k = 0; k < Kn; ++k) s += B1[tid * MS + k] * red[k];
            redu[tid] = s;
        }
        __syncthreads();
        if (tid < Kn) {
            float s = 0.f;
            for (int k = 0; k < Kn; ++k) s += B1[k * MS + tid] * redu[k];
            redu[64 + tid] = s;
        }
        __syncthreads();
        if (tid == 0) {
            float n = 0.f;
            for (int i = 0; i < Kn; ++i) n += redu[64 + i] * redu[64 + i];
            sc[1] = rsqrtf(fmaxf(n, 1e-30f));
        }
        __syncthreads();
        if (tid < Kn) red[tid] = redu[64 + tid] * sc[1];
        __syncthreads();
    }
    if (tid < Kn) {
        float s = 0.f;
        for (int k = 0; k < Kn; ++k) s += B1[tid * MS + k] * red[k];
        redu[tid] = s;
    }
    __syncthreads();
    if (tid == 0) {
        float n = 0.f;
        for (int i = 0; i < Kn; ++i) n += redu[i] * redu[i];
        float sigma = sqrtf(n);
        sc[2] = 0.98f / (sigma + 1e-6f);     // A scale
        sc[6] = sc[2] * Araw[0];             // scalar a (if diagonal)
    }
    // init P = I, z = 0; load Ls(0)
    for (int e = tid; e < Kn * Kn; e += NT) {
        int r = e >> 6, c = e & 63;
        Pm[r * MS + c] = (r == c) ? 1.f : 0.f;
    }
    if (tid < Kn) zv[tid] = 0.f;
    {
        const float4* Lg = (const float4*)Lam;
        for (int e4 = tid; e4 < (Nn * Kn) / 4; e4 += NT) {
            float4 v4 = Lg[e4];
            int i = e4 >> 4, c = (e4 & 15) << 2;
            *reinterpret_cast<float4*>(&Ls[i * MS + c]) = v4;
        }
    }
    __syncthreads();
    const int   scA   = sint[1];
    const int   unifR = sint[2];
    const float aA    = sc[6];
    const float ldD   = sc[0];
    const float crS   = sc[8];
    const float ascale = sc[2];

    // ------------------------------ main loop ------------------------------
#pragma unroll 1
    for (int t = 0; t < Tn; ++t) {
        // ---- A: Ppred -> B2 (full) and B1 (lower, zero upper); zpv ----
        if (scA) {
            float a2 = aA * aA;
            for (int e = tid; e < Kn * Kn; e += NT) {
                int a = e >> 6, b = e & 63;
                float v = a2 * Pm[a * MS + b];
                if (a == b) v += qd[a];
                B2[a * MS + b] = v;
                B1[a * MS + b] = (b <= a) ? v : 0.f;
            }
            if (tid < Kn) zpv[tid] = aA * zv[tid];
            __syncthreads();
        } else {
            for (int e = tid; e < Kn * Kn; e += NT)
                B6[(e >> 6) * MS + (e & 63)] = ascale * Araw[e];
            __syncthreads();
            g_nn(tid, B5, B6, Pm);                // B5 = A*P
            if (tid < Kn) {
                float s = 0.f;
                for (int k = 0; k < Kn; ++k) s += B6[tid * MS + k] * zv[k];
                zpv[tid] = s;
            }
            __syncthreads();
            g_nt_diag(tid, B2, B5, B6, qd);       // B2 = (A P)A^T + Q
            __syncthreads();
            for (int e = tid; e < Kn * Kn; e += NT) {
                int a = e >> 6, b = e & 63;
                B1[a * MS + b] = (b <= a) ? B2[a * MS + b] : 0.f;
            }
            __syncthreads();
        }

        // ---- B: innovation + weights (thread == channel) ----
        bool nanflag;
        {
            float y = obs[(size_t)t * Nn + tid];
            float yp = 0.f;
#pragma unroll 8
            for (int a = 0; a < Kn; ++a) yp += Ls[tid * MS + a] * zpv[a];
            nanflag = !(y == y);
            float vi = nanflag ? 0.f : (y - yp);
            float di = dinv[tid];
            wv[tid]  = vi * di;
            wmv[tid] = nanflag ? 0.f : di;
            w2v[tid] = nanflag ? 0.f : di * di;
            red[tid] = vi * vi * di;           // sdv terms
            unsigned bal = __ballot_sync(0xffffffffu, nanflag);
            if (lane == 0) sint[8 + warp] = (int)bal;
        }
        __syncthreads();

        // ---- C: u partials + masked-index compaction ----
        {
            int a = tid & 63, s4 = tid >> 6;
            float part = 0.f;
#pragma unroll 8
            for (int ii = 0; ii < 64; ++ii) {
                int i = s4 * 64 + ii;
                part += Ls[i * MS + a] * wv[i];
            }
            redu[tid] = part;
        }
        if (nanflag) {
            int base = 0;
            for (int k = 0; k < warp; ++k) base += __popc((unsigned)sint[8 + k]);
            base += __popc(((unsigned)sint[8 + warp]) & ((1u << lane) - 1u));
            midx[base] = tid;
        }
        if (tid == 0) {
            int nm = 0;
            for (int k = 0; k < 8; ++k) nm += __popc((unsigned)sint[8 + k]);
            sint[0] = nm;
            sc[3] = (float)(Nn - nm);
        }
        __syncthreads();
        const int nm = sint[0];

        // ---- D: warp0 chol(Ppred)=G  ||  warps1-7: u, SYRK, Wfull/Wr ----
        if (warp == 0) {
            // sdv = sum red (fixed order), then Cholesky
            float s = 0.f;
            for (int i = lane; i < Nn; i += 32) s += red[i];
#pragma unroll
            for (int o = 16; o > 0; o >>= 1) s += __shfl_down_sync(0xffffffffu, s, o);
            if (lane == 0) sc[4] = s;
            chol_warp(B1);                        // B1 = G (lower), upper stays 0
        } else {
            if (tid < 32 + Kn) {
                int a = tid - 32;
                uv[a] = redu[a] + redu[64 + a] + redu[128 + a] + redu[192 + a];
            }
            // lower-triangle 4x4 tiles of Wm (and W2 if non-uniform R)
            int tl = tid - 32;
            if (tl < 136) {
                int ti = 0;
                while (((ti + 1) * (ti + 2)) / 2 <= tl) ++ti;
                int tj = tl - (ti * (ti + 1)) / 2;
                int a = 4 * ti, b = 4 * tj;
                float m[4][4], q[4][4];
#pragma unroll
                for (int i = 0; i < 4; ++i)
#pragma unroll
                    for (int j = 0; j < 4; ++j) { m[i][j] = 0.f; q[i][j] = 0.f; }
                if (unifR) {
#pragma unroll 2
                    for (int i = 0; i < Nn; ++i) {
                        float cm = wmv[i];
                        float4 la = *reinterpret_cast<const float4*>(&Ls[i * MS + a]);
                        float4 lb = *reinterpret_cast<const float4*>(&Ls[i * MS + b]);
                        float law[4] = {cm * la.x, cm * la.y, cm * la.z, cm * la.w};
                        float lbv[4] = {lb.x, lb.y, lb.z, lb.w};
#pragma unroll
                        for (int ii = 0; ii < 4; ++ii)
#pragma unroll
                            for (int jj = 0; jj < 4; ++jj) m[ii][jj] += law[ii] * lbv[jj];
                    }
                } else {
#pragma unroll 2
                    for (int i = 0; i < Nn; ++i) {
                        float cm = wmv[i];
                        float4 la = *reinterpret_cast<const float4*>(&Ls[i * MS + a]);
                        float4 lb = *reinterpret_cast<const float4*>(&Ls[i * MS + b]);
                        float law[4] = {cm * la.x, cm * la.y, cm * la.z, cm * la.w};
                        float lbw[4] = {cm * lb.x, cm * lb.y, cm * lb.z, cm * lb.w};
                        float lbv[4] = {lb.x, lb.y, lb.z, lb.w};
#pragma unroll
                        for (int ii = 0; ii < 4; ++ii)
#pragma unroll
                            for (int jj = 0; jj < 4; ++jj) {
                                m[ii][jj] += law[ii] * lbv[jj];
                                q[ii][jj] += law[ii] * lbw[jj];  // m/d^2 weights
                            }
                    }
                }
#pragma unroll
                for (int ii = 0; ii < 4; ++ii)
#pragma unroll
                    for (int jj = 0; jj < 4; ++jj) {
                        B3[(a + ii) * MS + (b + jj)] = m[ii][jj];
                        if (!unifR) B4[(a + ii) * MS + (b + jj)] = q[ii][jj];
                    }
            }
            nbar(1, 224);
            // mirror + Wfull (B5) + Wr (B4) over lower triangle
            for (int e = tid - 32; e < Kn * Kn; e += (NT - 32)) {
                int a = e >> 6, b = e & 63;
                if (b > a) continue;
                float wm = B3[a * MS + b];
                float wr = unifR ? (crS * wm) : (wm - 1e-4f * B4[a * MS + b]);
                float wf = wm;
                for (int j = 0; j < nm; ++j) {
                    int ich = midx[j];
                    wf += dinv[ich] * Ls[ich * MS + a] * Ls[ich * MS + b];
                }
                B3[b * MS + a] = wm;
                B4[a * MS + b] = wr; B4[b * MS + a] = wr;
                B5[a * MS + b] = wf; B5[b * MS + a] = wf;
            }
        }
        __syncthreads();

        // ---- E1: WG = Wfull * G ----
        g_nn(tid, B6, B5, B1);
        __syncthreads();
        // ---- E2: Y + I = G^T * WG + I ----
        g_tn_I(tid, B5, B1, B6);
        __syncthreads();

        // ---- F: warp0 chol(Y+I)=H (logdet) || tids 64+ prefetch L(t+1) ----
        if (warp == 0) {
            float ld = chol_warp(B5);            // B5 lower = H
            if (lane == 0) sc[5] = ld;           // = logdetP + logdetM
        } else if (tid >= 64 && (t + 1) < Tn) {
            const float4* Lg = (const float4*)(Lam + (size_t)(t + 1) * Nn * Kn);
            for (int e4 = tid - 64; e4 < (Nn * Kn) / 4; e4 += (NT - 64)) {
                float4 v4 = Lg[e4];
                int i = e4 >> 4, c = (e4 & 15) << 2;
                *reinterpret_cast<float4*>(&Ls[i * MS + c]) = v4;
            }
        }
        __syncthreads();

        // ---- G: Hinv = H^{-1} by independent columns (tids 0..63) ----
        if (tid < Kn) colsolve(tid, B5, B6);
        __syncthreads();

        // ---- H1: E = G * Hinv^T ----
        g_nt(tid, B5, B1, B6);
        __syncthreads();
        // ---- H2: Minv = E * E^T ----
        g_nt(tid, B6, B5, B5);
        __syncthreads();

        // ---- I: x = Minv * u ----
        if (tid < Kn) {
            float s = 0.f;
#pragma unroll 8
            for (int k = 0; k < Kn; ++k) s += B6[tid * MS + k] * uv[k];
            xv[tid] = s;
        }
        __syncthreads();

        // ---- J: KGL = Minv * Wm ----
        g_nn(tid, B1, B6, B3);
        __syncthreads();

        // ---- K/L: KGRKG -> B4 ; tid0 computes quad ----
        if (tid == 0) {
            float q = 0.f;
            for (int i = 0; i < Kn; ++i) q += uv[i] * xv[i];
            sc[7] = q;
        }
        if (unifR) {
            // KGRKG = crS * KGL * Minv
            g_nn_scale(tid, B4, B1, B6, crS);
            __syncthreads();
        } else {
            g_nn(tid, B3, B6, B4);               // Ttmp = Minv*Wr (Wm dead)
            __syncthreads();
            g_nn(tid, B4, B3, B6);               // KGRKG = Ttmp*Minv
            __syncthreads();
        }

        // ---- M: T2 = Ppred - KGL*Ppred ----
        g_nn_rsub(tid, B5, B1, B2);
        __syncthreads();
        // ---- N: Pnew = T2 + KGRKG - T2*KGL^T ----
        g_joseph(tid, B6, B5, B1, B4);
        __syncthreads();

        // ---- O: symmetrize P; outputs ----
        for (int e = tid; e < Kn * Kn; e += NT) {
            int a = e >> 6, b = e & 63;
            Pm[a * MS + b] = 0.5f * (B6[a * MS + b] + B6[b * MS + a]);
        }
        if (tid < Kn) {
            float z = zpv[tid] + xv[tid];
            zv[tid] = z;
            out[(size_t)t * (Kn + 1) + tid] = z;
        }
        if (tid == 0) {
            float mahal = sc[4] - sc[7];
            float ll = -0.5f * (sc[3] * LOG2PI_F + ldD + sc[5] + mahal);
            if (!(ll == ll)) ll = -1e6f;
            out[(size_t)t * (Kn + 1) + Kn] = ll;
        }
        __syncthreads();
    }
}

extern "C" void kernel_launch(void* const* d_in, const int* in_sizes, int n_in,
                              void* d_out, int out_size)
{
    const float* obs  = (const float*)d_in[0];
    const float* Lam  = (const float*)d_in[1];
    const float* Araw = (const float*)d_in[2];
    const float* lQ   = (const float*)d_in[3];
    const float* lR   = (const float*)d_in[4];
    float* out = (float*)d_out;

    cudaFuncSetAttribute(kf_kernel, cudaFuncAttributeMaxDynamicSharedMemorySize,
                         SMEM_BYTES);
    kf_kernel<<<1, NT, SMEM_BYTES>>>(obs, Lam, Araw, lQ, lR, out);
}

// round 11
// speedup vs baseline: 2.8766x; 2.8720x over previous
#include <cuda_runtime.h>
#include <math.h>

#define NT 1024
#define Tn 2048
#define Nn 256
#define Kn 64
#define MSL 68          // Lambda row stride (float4-aligned)
#define MSM 65          // matrix row stride (odd -> conflict-free)
#define LOG2PI_F 1.8378770664093453f

#define SMEM_FLOATS (Nn*MSL + 8*Kn*MSM + 4*272 + 64 + 1024 + 256 + 4*Nn + Nn + 5*Kn + Nn + 16 + 16)
#define SMEM_BYTES (SMEM_FLOATS*4)

__device__ float gAm[Kn*Kn];   // scaled A for general (non-scalar) fallback

static __device__ __forceinline__ unsigned s2u(const void* p){
    unsigned a;
    asm("{ .reg .u64 t; cvta.to.shared.u64 t, %1; cvt.u32.u64 %0, t; }":"=r"(a):"l"(p));
    return a;
}
static __device__ __forceinline__ void cpa16(unsigned sa, const void* ga){
    asm volatile("cp.async.ca.shared.global [%0], [%1], 16;"::"r"(sa),"l"(ga));
}
static __device__ __forceinline__ void cpa_commit(){ asm volatile("cp.async.commit_group;"); }
static __device__ __forceinline__ void cpa_wait(){ asm volatile("cp.async.wait_group 0;"); }

// ============ 64x64 GEMMs, 1024 thr, 2x2: rows 2w,2w+1; cols l,l+32 =========
#define GHEAD int w=tid>>5,l=tid&31; int a0=w*2,a1=a0+1,b0=l,b1=l+32; \
    float c00=0.f,c01=0.f,c10=0.f,c11=0.f;

static __device__ __forceinline__ void g_nn(int tid,float* C,const float* X,const float* Y){
    GHEAD
#pragma unroll 8
    for(int k=0;k<Kn;++k){
        float x0=X[a0*MSM+k],x1=X[a1*MSM+k];
        float y0=Y[k*MSM+b0],y1=Y[k*MSM+b1];
        c00+=x0*y0;c01+=x0*y1;c10+=x1*y0;c11+=x1*y1;
    }
    C[a0*MSM+b0]=c00;C[a0*MSM+b1]=c01;C[a1*MSM+b0]=c10;C[a1*MSM+b1]=c11;
}
static __device__ __forceinline__ void g_nn_scale(int tid,float* C,const float* X,const float* Y,float s){
    GHEAD
#pragma unroll 8
    for(int k=0;k<Kn;++k){
        float x0=X[a0*MSM+k],x1=X[a1*MSM+k];
        float y0=Y[k*MSM+b0],y1=Y[k*MSM+b1];
        c00+=x0*y0;c01+=x0*y1;c10+=x1*y0;c11+=x1*y1;
    }
    C[a0*MSM+b0]=s*c00;C[a0*MSM+b1]=s*c01;C[a1*MSM+b0]=s*c10;C[a1*MSM+b1]=s*c11;
}
static __device__ __forceinline__ void g_tn_I(int tid,float* C,const float* X,const float* Y){
    GHEAD
#pragma unroll 8
    for(int k=0;k<Kn;++k){
        float x0=X[k*MSM+a0],x1=X[k*MSM+a1];
        float y0=Y[k*MSM+b0],y1=Y[k*MSM+b1];
        c00+=x0*y0;c01+=x0*y1;c10+=x1*y0;c11+=x1*y1;
    }
    if(a0==b0)c00+=1.f; if(a0==b1)c01+=1.f; if(a1==b0)c10+=1.f; if(a1==b1)c11+=1.f;
    C[a0*MSM+b0]=c00;C[a0*MSM+b1]=c01;C[a1*MSM+b0]=c10;C[a1*MSM+b1]=c11;
}
static __device__ __forceinline__ void g_nt(int tid,float* C,const float* X,const float* Y){
    GHEAD
#pragma unroll 8
    for(int k=0;k<Kn;++k){
        float x0=X[a0*MSM+k],x1=X[a1*MSM+k];
        float y0=Y[b0*MSM+k],y1=Y[b1*MSM+k];
        c00+=x0*y0;c01+=x0*y1;c10+=x1*y0;c11+=x1*y1;
    }
    C[a0*MSM+b0]=c00;C[a0*MSM+b1]=c01;C[a1*MSM+b0]=c10;C[a1*MSM+b1]=c11;
}
static __device__ __forceinline__ void g_nt_diag(int tid,float* C,const float* X,const float* Y,const float* dg){
    GHEAD
#pragma unroll 8
    for(int k=0;k<Kn;++k){
        float x0=X[a0*MSM+k],x1=X[a1*MSM+k];
        float y0=Y[b0*MSM+k],y1=Y[b1*MSM+k];
        c00+=x0*y0;c01+=x0*y1;c10+=x1*y0;c11+=x1*y1;
    }
    if(a0==b0)c00+=dg[a0]; if(a0==b1)c01+=dg[a0]; if(a1==b0)c10+=dg[a1]; if(a1==b1)c11+=dg[a1];
    C[a0*MSM+b0]=c00;C[a0*MSM+b1]=c01;C[a1*MSM+b0]=c10;C[a1*MSM+b1]=c11;
}
// C = Y - X*Y
static __device__ __forceinline__ void g_nn_rsub(int tid,float* C,const float* X,const float* Y){
    GHEAD
#pragma unroll 8
    for(int k=0;k<Kn;++k){
        float x0=X[a0*MSM+k],x1=X[a1*MSM+k];
        float y0=Y[k*MSM+b0],y1=Y[k*MSM+b1];
        c00+=x0*y0;c01+=x0*y1;c10+=x1*y0;c11+=x1*y1;
    }
    C[a0*MSM+b0]=Y[a0*MSM+b0]-c00; C[a0*MSM+b1]=Y[a0*MSM+b1]-c01;
    C[a1*MSM+b0]=Y[a1*MSM+b0]-c10; C[a1*MSM+b1]=Y[a1*MSM+b1]-c11;
}
// C = X + A2 - X*Y^T
static __device__ __forceinline__ void g_joseph(int tid,float* C,const float* X,const float* Y,const float* A2){
    GHEAD
#pragma unroll 8
    for(int k=0;k<Kn;++k){
        float x0=X[a0*MSM+k],x1=X[a1*MSM+k];
        float y0=Y[b0*MSM+k],y1=Y[b1*MSM+k];
        c00+=x0*y0;c01+=x0*y1;c10+=x1*y0;c11+=x1*y1;
    }
    C[a0*MSM+b0]=X[a0*MSM+b0]+A2[a0*MSM+b0]-c00;
    C[a0*MSM+b1]=X[a0*MSM+b1]+A2[a0*MSM+b1]-c01;
    C[a1*MSM+b0]=X[a1*MSM+b0]+A2[a1*MSM+b0]-c10;
    C[a1*MSM+b1]=X[a1*MSM+b1]+A2[a1*MSM+b1]-c11;
}

// ============ blocked Cholesky, NB=16, 4 panels, ~10 barriers ==============
// In-place lower. Writes 1/diag into invdv[64]. Optionally 2*sum(log diag).
static __device__ void chol_blk(float* __restrict__ A, float* __restrict__ invdv,
                                float* __restrict__ logOut)
{
    const int tid=threadIdx.x, lane=tid&31, warp=tid>>5;
    float plog=0.f;
#pragma unroll 1
    for(int p=0;p<4;++p){
        const int j0=p*16;
        if(warp==0){
            float a[16];
#pragma unroll
            for(int i=0;i<16;++i)
                a[i]=(lane<16 && i>=lane)?A[(j0+i)*MSM+j0+lane]:0.f;
            float prod=1.f;
#pragma unroll
            for(int j=0;j<16;++j){
                float dj=__shfl_sync(0xffffffffu,a[j],j);
                float d=sqrtf(dj), inv=1.f/d;
                prod*=d;
                if(lane==j){
                    a[j]=d;
#pragma unroll
                    for(int i=0;i<16;++i) if(i>j) a[i]*=inv;
                    invdv[j0+j]=inv;
                }
                float Lcj=0.f;
#pragma unroll
                for(int i=0;i<16;++i){
                    if(i>j){
                        float Lij=__shfl_sync(0xffffffffu,a[i],j);
                        if(i==lane) Lcj=Lij;
                        if(lane>j && i>=lane) a[i]-=Lij*Lcj;
                    }
                }
            }
            if(lane<16){
#pragma unroll
                for(int i=0;i<16;++i)
                    if(i>=lane) A[(j0+i)*MSM+j0+lane]=a[i];
            }
            if(lane==0) plog+=logf(prod);
        }
        __syncthreads();
        const int rem=48-16*p;
        if(rem>0){
            if(tid<rem){
                const int r=j0+16+tid;
                float x[16];
#pragma unroll
                for(int c=0;c<16;++c) x[c]=A[r*MSM+j0+c];
#pragma unroll
                for(int c=0;c<16;++c){
                    float s=x[c];
#pragma unroll
                    for(int k=0;k<16;++k) if(k<c) s-=x[k]*A[(j0+c)*MSM+j0+k];
                    x[c]=s*invdv[j0+c];
                }
#pragma unroll
                for(int c=0;c<16;++c) A[r*MSM+j0+c]=x[c];
            }
            __syncthreads();
            for(int e=tid;e<rem*rem;e+=NT){
                int i=e/rem, j2=e-i*rem;
                if(j2<=i){
                    int gi=j0+16+i, gj=j0+16+j2;
                    float s=0.f;
#pragma unroll
                    for(int k=0;k<16;++k) s+=A[gi*MSM+j0+k]*A[gj*MSM+j0+k];
                    A[gi*MSM+gj]-=s;
                }
            }
            __syncthreads();
        }
    }
    if(logOut && warp==0 && lane==0) *logOut=2.f*plog;
}

// ===========================================================================
__global__ __launch_bounds__(NT,1)
void kf_kernel(const float* __restrict__ obs, const float* __restrict__ Lam,
               const float* __restrict__ Araw, const float* __restrict__ logQ,
               const float* __restrict__ logR, float* __restrict__ out)
{
    extern __shared__ float sm[];
    float* Ls   = sm;                        // [256][68]
    float* Pm   = Ls + Nn*MSL;
    float* B1   = Pm + Kn*MSM;               // Ppred-lower -> G -> KGL-target later? (see phases)
    float* B2   = B1 + Kn*MSM;               // Ppred full
    float* B3   = B2 + Kn*MSM;               // Wm -> KGRKG(unifR) / Ttmp
    float* B4   = B3 + Kn*MSM;               // H -> KGL
    float* B5   = B4 + Kn*MSM;               // Wfull -> E -> T2
    float* B6   = B5 + Kn*MSM;               // WG -> Minv -> Pnew
    float* B7   = B6 + Kn*MSM;               // W2/Wr (non-uniform R only)
    float* invD = B7 + Kn*MSM;               // [4][16][17]
    float* invdv= invD + 4*272;              // [64]
    float* redu = invdv + 64;                // [1024]
    float* red  = redu + 1024;               // [256]
    float* wv   = red + 256;
    float* wmv  = wv + Nn;
    float* w2v  = wmv + Nn;
    float* dinv = w2v + Nn;
    int*   midx = (int*)(dinv + Nn);         // [256]
    float* zv   = (float*)(midx + Nn);
    float* zpv  = zv + Kn;
    float* uv   = zpv + Kn;
    float* xv   = uv + Kn;
    float* qd   = xv + Kn;
    float* obs_s= qd + Kn;                   // [256]
    float* sc   = obs_s + Nn;                // [16]
    int*   sint = (int*)(sc + 16);           // [16]

    const int tid=threadIdx.x, warp=tid>>5, lane=tid&31;

    // ------------------------------- prologue -------------------------------
    for(int e=tid;e<Kn*Kn;e+=NT) B1[(e>>6)*MSM+(e&63)]=Araw[e];
    if(tid<Kn) qd[tid]=expf(logQ[tid]);
    if(tid<Nn){ float r=expf(logR[tid]); dinv[tid]=1.f/(r+1e-4f); }
    if(tid==0) sint[1]=1;
    __syncthreads();
    if(tid==0){
        float ld=0.f; for(int i=0;i<Nn;++i) ld+=logf(1.f/dinv[i]);
        sc[0]=ld;
        int u=1; for(int i=1;i<Nn;++i) if(dinv[i]!=dinv[0]) u=0;
        sint[2]=u;
        sc[8]=1.f-1e-4f*dinv[0];
    }
    {   // exact scalar-A detect
        float a00=Araw[0]; int ok=1;
        for(int e=tid;e<Kn*Kn;e+=NT){
            int r=e>>6,c=e&63; float v=Araw[e];
            if(r==c){ if(v!=a00) ok=0; } else { if(v!=0.f) ok=0; }
        }
        if(!ok) atomicAnd(&sint[1],0);
    }
    // power iteration for sigma_max(A_raw)
    if(tid<Kn) redu[tid]=1.f;
    __syncthreads();
#pragma unroll 1
    for(int it=0;it<64;++it){
        if(tid<Kn){ float s=0.f; for(int k=0;k<Kn;++k) s+=B1[tid*MSM+k]*redu[k]; redu[256+tid]=s; }
        __syncthreads();
        if(tid<Kn){ float s=0.f; for(int k=0;k<Kn;++k) s+=B1[k*MSM+tid]*redu[256+k]; redu[512+tid]=s; }
        __syncthreads();
        if(tid==0){
            float n=0.f; for(int i=0;i<Kn;++i) n+=redu[512+i]*redu[512+i];
            sc[1]=rsqrtf(fmaxf(n,1e-30f));
        }
        __syncthreads();
        if(tid<Kn) redu[tid]=redu[512+tid]*sc[1];
        __syncthreads();
    }
    if(tid<Kn){ float s=0.f; for(int k=0;k<Kn;++k) s+=B1[tid*MSM+k]*redu[k]; redu[256+tid]=s; }
    __syncthreads();
    if(tid==0){
        float n=0.f; for(int i=0;i<Kn;++i) n+=redu[256+i]*redu[256+i];
        float sigma=sqrtf(n);
        sc[2]=0.98f/(sigma+1e-6f);
        sc[6]=sc[2]*Araw[0];
    }
    __syncthreads();
    // general-A: stage scaled A in global (constant across steps)
    if(!sint[1]){ float s=sc[2]; for(int e=tid;e<Kn*Kn;e+=NT) gAm[e]=s*Araw[e]; }
    // init P=I, z=0; load Ls(0), obs(0)
    for(int e=tid;e<Kn*Kn;e+=NT){ int r=e>>6,c=e&63; Pm[r*MSM+c]=(r==c)?1.f:0.f; }
    if(tid<Kn) zv[tid]=0.f;
    {
        const float4* Lg=(const float4*)Lam;
        for(int e4=tid;e4<(Nn*Kn)/4;e4+=NT){
            float4 v4=Lg[e4]; int i=e4>>4,c=(e4&15)<<2;
            *reinterpret_cast<float4*>(&Ls[i*MSL+c])=v4;
        }
        if(tid<Nn) obs_s[tid]=obs[tid];
    }
    __syncthreads();
    const int scA=sint[1], unifR=sint[2];
    const float aA=sc[6], ldD=sc[0], crS=sc[8];

    // SYRK lower-tile mapping (32x32 grid of 2x2 tiles, 528 lower tiles)
    int s_ti=0,s_tj=0;
    if(tid<528){
        int ti=0; while((ti+1)*(ti+2)/2<=tid) ++ti;
        s_ti=ti; s_tj=tid-ti*(ti+1)/2;
    }

    // ------------------------------- main loop ------------------------------
#pragma unroll 1
    for(int t=0;t<Tn;++t){
        // P1: Ppred -> B2 full, B1 lower(zero upper); zpv
        if(scA){
            float a2=aA*aA;
            for(int e=tid;e<Kn*Kn;e+=NT){
                int a=e>>6,b=e&63;
                float v=a2*Pm[a*MSM+b]; if(a==b) v+=qd[a];
                B2[a*MSM+b]=v; B1[a*MSM+b]=(b<=a)?v:0.f;
            }
            if(tid<Kn) zpv[tid]=aA*zv[tid];
        } else {
            for(int e=tid;e<Kn*Kn;e+=NT) B6[(e>>6)*MSM+(e&63)]=gAm[e];
            __syncthreads();
            g_nn(tid,B5,B6,Pm);
            if(tid<Kn){ float s=0.f; for(int k=0;k<Kn;++k) s+=B6[tid*MSM+k]*zv[k]; zpv[tid]=s; }
            __syncthreads();
            g_nt_diag(tid,B2,B5,B6,qd);
            __syncthreads();
            for(int e=tid;e<Kn*Kn;e+=NT){
                int a=e>>6,b=e&63;
                B1[a*MSM+b]=(b<=a)?B2[a*MSM+b]:0.f;
            }
        }
        cpa_wait();            // Ls(t)/obs(t) prefetch (no-op at t=0)
        __syncthreads();

        // P2: innovation + weights (tid<256)
        bool nanflag=false;
        if(tid<Nn){
            float y=obs_s[tid];
            float yp=0.f;
#pragma unroll 8
            for(int a=0;a<Kn;++a) yp+=Ls[tid*MSL+a]*zpv[a];
            nanflag=!(y==y);
            float vi=nanflag?0.f:(y-yp);
            float di=dinv[tid];
            wv[tid]=vi*di;
            wmv[tid]=nanflag?0.f:di;
            w2v[tid]=nanflag?0.f:di*di;
            red[tid]=vi*vi*di;
            unsigned bal=__ballot_sync(0xffffffffu,nanflag);
            if(lane==0) sint[8+warp]=(int)bal;
        }
        __syncthreads();

        // P3: u partials + NaN compaction
        {
            int a=tid&63, s4=tid>>6;
            float part=0.f;
#pragma unroll
            for(int ii=0;ii<16;++ii){ int i=s4*16+ii; part+=Ls[i*MSL+a]*wv[i]; }
            redu[tid]=part;
        }
        if(nanflag){
            int base=0;
            for(int k=0;k<warp;++k) base+=__popc((unsigned)sint[8+k]);
            base+=__popc(((unsigned)sint[8+warp])&((1u<<lane)-1u));
            midx[base]=tid;
        }
        if(tid==0){
            int nm2=0; for(int k=0;k<8;++k) nm2+=__popc((unsigned)sint[8+k]);
            sint[0]=nm2; sc[3]=(float)(Nn-nm2);
        }
        __syncthreads();
        const int nm=sint[0];

        // P4: SYRK lower tiles (tid<528) || sdv (warp 28) || uv (tids 960+)
        if(tid<528){
            int a0=2*s_ti,a1=a0+1,b0=2*s_tj,b1=b0+1;
            float m00=0.f,m01=0.f,m10=0.f,m11=0.f;
            float q00=0.f,q01=0.f,q10=0.f,q11=0.f;
            if(unifR){
#pragma unroll 4
                for(int i=0;i<Nn;++i){
                    float cm=wmv[i];
                    float la0=cm*Ls[i*MSL+a0], la1=cm*Ls[i*MSL+a1];
                    float lb0=Ls[i*MSL+b0], lb1=Ls[i*MSL+b1];
                    m00+=la0*lb0;m01+=la0*lb1;m10+=la1*lb0;m11+=la1*lb1;
                }
            } else {
#pragma unroll 2
                for(int i=0;i<Nn;++i){
                    float cm=wmv[i], c2=w2v[i];
                    float la0=Ls[i*MSL+a0], la1=Ls[i*MSL+a1];
                    float lb0=Ls[i*MSL+b0], lb1=Ls[i*MSL+b1];
                    float p00=la0*lb0,p01=la0*lb1,p10=la1*lb0,p11=la1*lb1;
                    m00+=cm*p00;m01+=cm*p01;m10+=cm*p10;m11+=cm*p11;
                    q00+=c2*p00;q01+=c2*p01;q10+=c2*p10;q11+=c2*p11;
                }
            }
            B3[a0*MSM+b0]=m00;B3[a0*MSM+b1]=m01;B3[a1*MSM+b0]=m10;B3[a1*MSM+b1]=m11;
            if(!unifR){
                B7[a0*MSM+b0]=q00;B7[a0*MSM+b1]=q01;B7[a1*MSM+b0]=q10;B7[a1*MSM+b1]=q11;
            }
        } else if(warp==28){
            float s=0.f;
            for(int i=lane;i<Nn;i+=32) s+=red[i];
#pragma unroll
            for(int o=16;o>0;o>>=1) s+=__shfl_down_sync(0xffffffffu,s,o);
            if(lane==0) sc[4]=s;
        } else if(tid>=960){
            int a=tid-960;
            float s=0.f;
#pragma unroll
            for(int s4=0;s4<16;++s4) s+=redu[s4*64+a];
            uv[a]=s;
        }
        __syncthreads();

        // P5: mirror Wm; Wfull (B5, both tri); Wr (B7) if non-uniform R
        for(int e=tid;e<Kn*Kn;e+=NT){
            int a=e>>6,b=e&63;
            if(b>a) continue;
            float wm=B3[a*MSM+b];
            float wf=wm;
            for(int j=0;j<nm;++j){
                int ich=midx[j];
                wf+=dinv[ich]*Ls[ich*MSL+a]*Ls[ich*MSL+b];
            }
            B3[b*MSM+a]=wm;
            B5[a*MSM+b]=wf; B5[b*MSM+a]=wf;
            if(!unifR){
                float wr=wm-1e-4f*B7[a*MSM+b];
                B7[a*MSM+b]=wr; B7[b*MSM+a]=wr;
            }
        }
        __syncthreads();

        // prefetch Lambda(t+1), obs(t+1) — Ls dead from here on
        if(t+1<Tn){
            const float* Lg=Lam+(size_t)(t+1)*Nn*Kn;
            unsigned base=s2u(Ls);
#pragma unroll
            for(int r=0;r<4;++r){
                int e4=tid+r*NT;
                int i=e4>>4,c=(e4&15)<<2;
                cpa16(base+(unsigned)(i*MSL+c)*4u, Lg+e4*4);
            }
            if(tid<64) cpa16(s2u(obs_s)+(unsigned)tid*16u, obs+(size_t)(t+1)*Nn+tid*4);
            cpa_commit();
        }

        // P6: G = chol(Ppred) in B1
        chol_blk(B1,invdv,0);

        // P7/P8: WG = Wfull*G ; Y+I = G^T*WG + I
        g_nn(tid,B6,B5,B1);
        __syncthreads();
        g_tn_I(tid,B4,B1,B6);
        __syncthreads();

        // P9: H = chol(Y+I) in B4; logdetP+logdetM -> sc[5]
        chol_blk(B4,invdv,&sc[5]);

        // P10: 16x16 diag-block inverses of H (tids 0..63)
        if(tid<64){
            int p=tid>>4, cc=tid&15;
            const float* D=&B4[(p*16)*MSM+p*16];
            float col[16];
#pragma unroll
            for(int i=0;i<16;++i){
                if(i<cc) col[i]=0.f;
                else{
                    float s=(i==cc)?1.f:0.f;
#pragma unroll
                    for(int k=0;k<16;++k) if(k>=cc&&k<i) s-=D[i*MSM+k]*col[k];
                    col[i]=s*invdv[p*16+i];
                }
            }
#pragma unroll
            for(int i=0;i<16;++i) invD[p*272+i*17+cc]=col[i];
        }
        __syncthreads();

        // P11: E (B5) via blocked trsm: E H^T = G  (4 block steps)
#pragma unroll 1
        for(int jb=0;jb<4;++jb){
            int j0=jb*16;
            {
                int r=tid>>4, c=tid&15;
                float s=B1[r*MSM+j0+c];
                for(int k=0;k<j0;++k) s-=B5[r*MSM+k]*B4[(j0+c)*MSM+k];
                redu[r*16+c]=s;
            }
            __syncthreads();
            {
                int r=tid>>4, cc=tid&15;
                float s=0.f;
#pragma unroll
                for(int c=0;c<16;++c) if(c<=cc) s+=redu[r*16+c]*invD[jb*272+cc*17+c];
                B5[r*MSM+j0+cc]=s;
            }
            __syncthreads();
        }

        // P12: Minv = E*E^T -> B6
        g_nt(tid,B6,B5,B5);
        __syncthreads();

        // P13: x = Minv*u
        if(tid<Kn){
            float s=0.f;
#pragma unroll 8
            for(int k=0;k<Kn;++k) s+=B6[tid*MSM+k]*uv[k];
            xv[tid]=s;
        }
        __syncthreads();

        // P14: KGL = Minv*Wm -> B4 (H dead)
        g_nn(tid,B4,B6,B3);
        __syncthreads();

        // P15: KGRKG
        const float* KGRKG;
        if(unifR){
            g_nn_scale(tid,B3,B4,B6,crS);      // B3 = crS*KGL*Minv (Wm dead)
            KGRKG=B3;
            __syncthreads();
        } else {
            g_nn(tid,B3,B6,B7);                // Ttmp = Minv*Wr
            __syncthreads();
            g_nn(tid,B7,B3,B6);                // KGRKG = Ttmp*Minv
            KGRKG=B7;
            __syncthreads();
        }

        // P16: T2 = Ppred - KGL*Ppred -> B5 (E dead)
        g_nn_rsub(tid,B5,B4,B2);
        __syncthreads();
        // P17: Pnew = T2 + KGRKG - T2*KGL^T -> B6 (Minv dead)
        g_joseph(tid,B6,B5,B4,KGRKG);
        __syncthreads();

        // P18: symmetrize; outputs
        for(int e=tid;e<Kn*Kn;e+=NT){
            int a=e>>6,b=e&63;
            Pm[a*MSM+b]=0.5f*(B6[a*MSM+b]+B6[b*MSM+a]);
        }
        if(tid<Kn){
            float z=zpv[tid]+xv[tid];
            zv[tid]=z;
            out[(size_t)t*(Kn+1)+tid]=z;
        }
        if(tid==0){
            float quad=0.f;
            for(int i=0;i<Kn;++i) quad+=uv[i]*xv[i];
            float mahal=sc[4]-quad;
            float ll=-0.5f*(sc[3]*LOG2PI_F+ldD+sc[5]+mahal);
            if(!(ll==ll)) ll=-1e6f;
            out[(size_t)t*(Kn+1)+Kn]=ll;
        }
        __syncthreads();
    }
}

extern "C" void kernel_launch(void* const* d_in, const int* in_sizes, int n_in,
                              void* d_out, int out_size)
{
    const float* obs =(const float*)d_in[0];
    const float* Lam =(const float*)d_in[1];
    const float* Araw=(const float*)d_in[2];
    const float* lQ  =(const float*)d_in[3];
    const float* lR  =(const float*)d_in[4];
    float* out=(float*)d_out;

    cudaFuncSetAttribute(kf_kernel, cudaFuncAttributeMaxDynamicSharedMemorySize,
                         SMEM_BYTES);
    kf_kernel<<<1, NT, SMEM_BYTES>>>(obs, Lam, Araw, lQ, lR, out);
}

// round 13
// speedup vs baseline: 3.3371x; 1.1601x over previous
#include <cuda_runtime.h>
#include <math.h>

#define NT 1024
#define Tn 2048
#define Nn 256
#define Kn 64
#define MSL 68          // Lambda row stride (float4-aligned)
#define MSM 65          // matrix row stride (odd -> conflict-free; SCALAR access only!)
#define LOG2PI_F 1.8378770664093453f

#define SMEM_FLOATS (Nn*MSL + 8*Kn*MSM + 4*272 + 64 + 1024 + 256 + 4*Nn + Nn + 5*Kn + Nn + 16 + 16)
#define SMEM_BYTES (SMEM_FLOATS*4)

__device__ float gAm[Kn*Kn];   // scaled A for general (non-scalar) fallback

static __device__ __forceinline__ unsigned s2u(const void* p){
    unsigned a;
    asm("{ .reg .u64 t; cvta.to.shared.u64 t, %1; cvt.u32.u64 %0, t; }":"=r"(a):"l"(p));
    return a;
}
static __device__ __forceinline__ void cpa16(unsigned sa, const void* ga){
    asm volatile("cp.async.ca.shared.global [%0], [%1], 16;"::"r"(sa),"l"(ga));
}
static __device__ __forceinline__ void cpa_commit(){ asm volatile("cp.async.commit_group;"); }
static __device__ __forceinline__ void cpa_wait(){ asm volatile("cp.async.wait_group 0;"); }
static __device__ __forceinline__ void nbar(int id, int cnt){
    asm volatile("bar.sync %0, %1;" :: "r"(id), "r"(cnt) : "memory");
}

// ============ full 64x64 GEMMs, 1024 thr, rows 2w,2w+1; cols l,l+32 =========
#define GHEAD int w=tid>>5,l=tid&31; int a0=w*2,a1=a0+1,b0=l,b1=l+32; \
    float c00=0.f,c01=0.f,c10=0.f,c11=0.f;

static __device__ __forceinline__ void g_nn(int tid,float* C,const float* X,const float* Y){
    GHEAD
#pragma unroll 8
    for(int k=0;k<Kn;++k){
        float x0=X[a0*MSM+k],x1=X[a1*MSM+k];
        float y0=Y[k*MSM+b0],y1=Y[k*MSM+b1];
        c00+=x0*y0;c01+=x0*y1;c10+=x1*y0;c11+=x1*y1;
    }
    C[a0*MSM+b0]=c00;C[a0*MSM+b1]=c01;C[a1*MSM+b0]=c10;C[a1*MSM+b1]=c11;
}
static __device__ __forceinline__ void g_nt_diag(int tid,float* C,const float* X,const float* Y,const float* dg){
    GHEAD
#pragma unroll 8
    for(int k=0;k<Kn;++k){
        float x0=X[a0*MSM+k],x1=X[a1*MSM+k];
        float y0=Y[b0*MSM+k],y1=Y[b1*MSM+k];
        c00+=x0*y0;c01+=x0*y1;c10+=x1*y0;c11+=x1*y1;
    }
    if(a0==b0)c00+=dg[a0]; if(a0==b1)c01+=dg[a0]; if(a1==b0)c10+=dg[a1]; if(a1==b1)c11+=dg[a1];
    C[a0*MSM+b0]=c00;C[a0*MSM+b1]=c01;C[a1*MSM+b0]=c10;C[a1*MSM+b1]=c11;
}
// C = Y - X*Y
static __device__ __forceinline__ void g_nn_rsub(int tid,float* C,const float* X,const float* Y){
    GHEAD
#pragma unroll 8
    for(int k=0;k<Kn;++k){
        float x0=X[a0*MSM+k],x1=X[a1*MSM+k];
        float y0=Y[k*MSM+b0],y1=Y[k*MSM+b1];
        c00+=x0*y0;c01+=x0*y1;c10+=x1*y0;c11+=x1*y1;
    }
    C[a0*MSM+b0]=Y[a0*MSM+b0]-c00; C[a0*MSM+b1]=Y[a0*MSM+b1]-c01;
    C[a1*MSM+b0]=Y[a1*MSM+b0]-c10; C[a1*MSM+b1]=Y[a1*MSM+b1]-c11;
}
// WG = X * G with G lower-triangular: warp w owns cols 2w,2w+1; loop k>=2w.
static __device__ __forceinline__ void g_nn_lowY(int tid,float* C,const float* X,const float* G){
    int w=tid>>5,l=tid&31;
    int c0=2*w,c1=c0+1;
    float c00=0.f,c01=0.f,c10=0.f,c11=0.f;
    for(int k=c0;k<Kn;++k){
        float g0=G[k*MSM+c0], g1=G[k*MSM+c1];   // upper of G is zero
        float x0=X[l*MSM+k],  x1=X[(l+32)*MSM+k];
        c00+=x0*g0;c01+=x0*g1;c10+=x1*g0;c11+=x1*g1;
    }
    C[l*MSM+c0]=c00; C[l*MSM+c1]=c01;
    C[(l+32)*MSM+c0]=c10; C[(l+32)*MSM+c1]=c11;
}

// ============ blocked Cholesky, NB=16, group-parameterized ==================
// Threads [base, base+cnt) participate; internal barriers use nbar(barid,cnt).
static __device__ void chol_grp(float* __restrict__ A, float* __restrict__ invdv,
                                float* __restrict__ logOut,
                                int base, int cnt, int barid)
{
    const int tg=(int)threadIdx.x-base, lane=tg&31;
    float plog=0.f;
#pragma unroll 1
    for(int p=0;p<4;++p){
        const int j0=p*16;
        if(tg>=0 && tg<32){
            float a[16];
#pragma unroll
            for(int i=0;i<16;++i)
                a[i]=(lane<16 && i>=lane)?A[(j0+i)*MSM+j0+lane]:0.f;
            float prod=1.f;
#pragma unroll
            for(int j=0;j<16;++j){
                float dj=__shfl_sync(0xffffffffu,a[j],j);
                float d=sqrtf(dj), inv=1.f/d;
                prod*=d;
                if(lane==j){
                    a[j]=d;
#pragma unroll
                    for(int i=0;i<16;++i) if(i>j) a[i]*=inv;
                    invdv[j0+j]=inv;
                }
                float Lcj=0.f;
#pragma unroll
                for(int i=0;i<16;++i){
                    if(i>j){
                        float Lij=__shfl_sync(0xffffffffu,a[i],j);
                        if(i==lane) Lcj=Lij;
                        if(lane>j && i>=lane) a[i]-=Lij*Lcj;
                    }
                }
            }
            if(lane<16){
#pragma unroll
                for(int i=0;i<16;++i)
                    if(i>=lane) A[(j0+i)*MSM+j0+lane]=a[i];
            }
            if(lane==0) plog+=logf(prod);
        }
        nbar(barid,cnt);
        const int rem=48-16*p;
        if(rem>0){
            if(tg>=0 && tg<rem){
                const int r=j0+16+tg;
                float x[16];
#pragma unroll
                for(int c=0;c<16;++c) x[c]=A[r*MSM+j0+c];
#pragma unroll
                for(int c=0;c<16;++c){
                    float s=x[c];
#pragma unroll
                    for(int k=0;k<16;++k) if(k<c) s-=x[k]*A[(j0+c)*MSM+j0+k];
                    x[c]=s*invdv[j0+c];
                }
#pragma unroll
                for(int c=0;c<16;++c) A[r*MSM+j0+c]=x[c];
            }
            nbar(barid,cnt);
            for(int e=tg;e<rem*rem;e+=cnt){
                int i=e/rem, j2=e-i*rem;
                if(j2<=i){
                    int gi=j0+16+i, gj=j0+16+j2;
                    float s=0.f;
#pragma unroll
                    for(int k=0;k<16;++k) s+=A[gi*MSM+j0+k]*A[gj*MSM+j0+k];
                    A[gi*MSM+gj]-=s;
                }
            }
            nbar(barid,cnt);
        }
    }
    if(logOut && tg==0) *logOut=2.f*plog;
}

// ===========================================================================
__global__ __launch_bounds__(NT,1)
void kf_kernel(const float* __restrict__ obs, const float* __restrict__ Lam,
               const float* __restrict__ Araw, const float* __restrict__ logQ,
               const float* __restrict__ logR, float* __restrict__ out)
{
    extern __shared__ float sm[];
    float* Ls   = sm;                        // [256][68]
    float* Pm   = Ls + Nn*MSL;
    float* B1   = Pm + Kn*MSM;               // Ppred-lower -> G
    float* B2   = B1 + Kn*MSM;               // Ppred full
    float* B3   = B2 + Kn*MSM;               // Wm -> KGRKG
    float* B4   = B3 + Kn*MSM;               // Y+I/H -> KGL
    float* B5   = B4 + Kn*MSM;               // Wfull -> E -> T2
    float* B6   = B5 + Kn*MSM;               // WG -> Minv
    float* B7   = B6 + Kn*MSM;               // SYRK scratch (unifR) / W2,Wr (fallback)
    float* invD = B7 + Kn*MSM;               // [4][16][17]
    float* invdv= invD + 4*272;              // [64]
    float* redu = invdv + 64;                // [1024]
    float* red  = redu + 1024;               // [256]
    float* wv   = red + 256;
    float* wmv  = wv + Nn;
    float* w2v  = wmv + Nn;
    float* dinv = w2v + Nn;
    int*   midx = (int*)(dinv + Nn);         // [256]
    float* zv   = (float*)(midx + Nn);
    float* zpv  = zv + Kn;
    float* uv   = zpv + Kn;
    float* xv   = uv + Kn;
    float* qd   = xv + Kn;
    float* obs_s= qd + Kn;                   // [256]
    float* sc   = obs_s + Nn;                // [16]
    int*   sint = (int*)(sc + 16);           // [16]

    const int tid=threadIdx.x, warp=tid>>5, lane=tid&31;

    // ------------------------------- prologue -------------------------------
    for(int e=tid;e<Kn*Kn;e+=NT) B1[(e>>6)*MSM+(e&63)]=Araw[e];
    if(tid<Kn) qd[tid]=expf(logQ[tid]);
    if(tid<Nn){ float r=expf(logR[tid]); dinv[tid]=1.f/(r+1e-4f); }
    if(tid==0) sint[1]=1;
    __syncthreads();
    if(tid==0){
        float ld=0.f; for(int i=0;i<Nn;++i) ld+=logf(1.f/dinv[i]);
        sc[0]=ld;
        int u=1; for(int i=1;i<Nn;++i) if(dinv[i]!=dinv[0]) u=0;
        sint[2]=u;
        sc[8]=1.f-1e-4f*dinv[0];
    }
    {   // exact scalar-A detect
        float a00=Araw[0]; int ok=1;
        for(int e=tid;e<Kn*Kn;e+=NT){
            int r=e>>6,c=e&63; float v=Araw[e];
            if(r==c){ if(v!=a00) ok=0; } else { if(v!=0.f) ok=0; }
        }
        if(!ok) atomicAnd(&sint[1],0);
    }
    // power iteration for sigma_max(A_raw)
    if(tid<Kn) redu[tid]=1.f;
    __syncthreads();
#pragma unroll 1
    for(int it=0;it<64;++it){
        if(tid<Kn){ float s=0.f; for(int k=0;k<Kn;++k) s+=B1[tid*MSM+k]*redu[k]; redu[256+tid]=s; }
        __syncthreads();
        if(tid<Kn){ float s=0.f; for(int k=0;k<Kn;++k) s+=B1[k*MSM+tid]*redu[256+k]; redu[512+tid]=s; }
        __syncthreads();
        if(tid==0){
            float n=0.f; for(int i=0;i<Kn;++i) n+=redu[512+i]*redu[512+i];
            sc[1]=rsqrtf(fmaxf(n,1e-30f));
        }
        __syncthreads();
        if(tid<Kn) redu[tid]=redu[512+tid]*sc[1];
        __syncthreads();
    }
    if(tid<Kn){ float s=0.f; for(int k=0;k<Kn;++k) s+=B1[tid*MSM+k]*redu[k]; redu[256+tid]=s; }
    __syncthreads();
    if(tid==0){
        float n=0.f; for(int i=0;i<Kn;++i) n+=redu[256+i]*redu[256+i];
        float sigma=sqrtf(n);
        sc[2]=0.98f/(sigma+1e-6f);
        sc[6]=sc[2]*Araw[0];
    }
    __syncthreads();
    if(!sint[1]){ float s=sc[2]; for(int e=tid;e<Kn*Kn;e+=NT) gAm[e]=s*Araw[e]; }
    for(int e=tid;e<Kn*Kn;e+=NT){ int r=e>>6,c=e&63; Pm[r*MSM+c]=(r==c)?1.f:0.f; }
    if(tid<Kn) zv[tid]=0.f;
    {
        const float4* Lg=(const float4*)Lam;
        for(int e4=tid;e4<(Nn*Kn)/4;e4+=NT){
            float4 v4=Lg[e4]; int i=e4>>4,c=(e4&15)<<2;
            *reinterpret_cast<float4*>(&Ls[i*MSL+c])=v4;
        }
        if(tid<Nn) obs_s[tid]=obs[tid];
    }
    __syncthreads();
    const int scA=sint[1], unifR=sint[2];
    const float aA=sc[6], ldD=sc[0], crS=sc[8];

    // 2x2 lower-tile map (528 tiles on 32x32 grid)
    int s_ti=0,s_tj=0;
    if(tid<528){
        int ti=0; while((ti+1)*(ti+2)/2<=tid) ++ti;
        s_ti=ti; s_tj=tid-ti*(ti+1)/2;
    }
    // 4x4 lower-tile map with 2-way i-split (272 threads, 136 tiles)
    int t4_ti=0,t4_tj=0,t4_half=0;
    if(tid<272){
        t4_half=tid/136;
        int tile=tid-t4_half*136;
        int ti=0; while((ti+1)*(ti+2)/2<=tile) ++ti;
        t4_ti=ti; t4_tj=tile-ti*(ti+1)/2;
    }

    // ------------------------------- main loop ------------------------------
#pragma unroll 1
    for(int t=0;t<Tn;++t){
        // P1: Ppred -> B2 full, B1 lower(zero upper); zpv
        if(scA){
            float a2=aA*aA;
            for(int e=tid;e<Kn*Kn;e+=NT){
                int a=e>>6,b=e&63;
                float v=a2*Pm[a*MSM+b]; if(a==b) v+=qd[a];
                B2[a*MSM+b]=v; B1[a*MSM+b]=(b<=a)?v:0.f;
            }
            if(tid<Kn) zpv[tid]=aA*zv[tid];
        } else {
            for(int e=tid;e<Kn*Kn;e+=NT) B6[(e>>6)*MSM+(e&63)]=gAm[e];
            __syncthreads();
            g_nn(tid,B5,B6,Pm);
            if(tid<Kn){ float s=0.f; for(int k=0;k<Kn;++k) s+=B6[tid*MSM+k]*zv[k]; zpv[tid]=s; }
            __syncthreads();
            g_nt_diag(tid,B2,B5,B6,qd);
            __syncthreads();
            for(int e=tid;e<Kn*Kn;e+=NT){
                int a=e>>6,b=e&63;
                B1[a*MSM+b]=(b<=a)?B2[a*MSM+b]:0.f;
            }
        }
        cpa_wait();
        __syncthreads();

        // P2: innovation + weights (tid<256)
        bool nanflag=false;
        if(tid<Nn){
            float y=obs_s[tid];
            float yp=0.f;
#pragma unroll 8
            for(int a=0;a<Kn;++a) yp+=Ls[tid*MSL+a]*zpv[a];
            nanflag=!(y==y);
            float vi=nanflag?0.f:(y-yp);
            float di=dinv[tid];
            wv[tid]=vi*di;
            wmv[tid]=nanflag?0.f:di;
            if(!unifR) w2v[tid]=nanflag?0.f:di*di;
            red[tid]=vi*vi*di;
            unsigned bal=__ballot_sync(0xffffffffu,nanflag);
            if(lane==0) sint[8+warp]=(int)bal;
        }
        __syncthreads();

        // P3: u partials (tid<256, 4 segments x 64) + NaN compaction
        if(tid<Nn){
            int a=tid&63, s4=tid>>6;
            float part=0.f;
#pragma unroll 8
            for(int ii=0;ii<64;++ii){ int i=s4*64+ii; part+=Ls[i*MSL+a]*wv[i]; }
            redu[s4*64+a]=part;
            if(nanflag){
                int base=0;
                for(int k=0;k<warp;++k) base+=__popc((unsigned)sint[8+k]);
                base+=__popc(((unsigned)sint[8+warp])&((1u<<lane)-1u));
                midx[base]=tid;
            }
            if(tid==0){
                int nm2=0; for(int k=0;k<8;++k) nm2+=__popc((unsigned)sint[8+k]);
                sint[0]=nm2; sc[3]=(float)(Nn-nm2);
            }
        }
        __syncthreads();
        const int nm=sint[0];

        // P4: group A (tid<384): SYRK + sdv + uv + merge + Wfull + prefetch
        //     group B (tid>=384): chol(Ppred)=G   — concurrent
        if(unifR){
            if(tid<384){
                if(tid<272){
                    const int a=4*t4_ti, b=4*t4_tj;
                    float A0x=0,A0y=0,A0z=0,A0w=0, A1x=0,A1y=0,A1z=0,A1w=0;
                    float A2x=0,A2y=0,A2z=0,A2w=0, A3x=0,A3y=0,A3z=0,A3w=0;
                    const int i0=t4_half*128;
#pragma unroll 2
                    for(int i=i0;i<i0+128;++i){
                        float cm=wmv[i];
                        float4 la=*reinterpret_cast<const float4*>(&Ls[i*MSL+a]);
                        float4 lb=*reinterpret_cast<const float4*>(&Ls[i*MSL+b]);
                        float w0=cm*la.x, w1=cm*la.y, w2=cm*la.z, w3=cm*la.w;
                        A0x+=w0*lb.x;A0y+=w0*lb.y;A0z+=w0*lb.z;A0w+=w0*lb.w;
                        A1x+=w1*lb.x;A1y+=w1*lb.y;A1z+=w1*lb.z;A1w+=w1*lb.w;
                        A2x+=w2*lb.x;A2y+=w2*lb.y;A2z+=w2*lb.z;A2w+=w2*lb.w;
                        A3x+=w3*lb.x;A3y+=w3*lb.y;A3z+=w3*lb.z;A3w+=w3*lb.w;
                    }
                    if(t4_half==0){
                        // SCALAR stores: MSM=65 (odd) -> float4 would misalign
                        float* r0=&B3[(a+0)*MSM+b];
                        r0[0]=A0x;r0[1]=A0y;r0[2]=A0z;r0[3]=A0w;
                        float* r1=&B3[(a+1)*MSM+b];
                        r1[0]=A1x;r1[1]=A1y;r1[2]=A1z;r1[3]=A1w;
                        float* r2=&B3[(a+2)*MSM+b];
                        r2[0]=A2x;r2[1]=A2y;r2[2]=A2z;r2[3]=A2w;
                        float* r3=&B3[(a+3)*MSM+b];
                        r3[0]=A3x;r3[1]=A3y;r3[2]=A3z;r3[3]=A3w;
                    } else {
                        float* d=&B7[(tid-136)*16];   // flat scratch, 16B-aligned
                        *reinterpret_cast<float4*>(d+0) =make_float4(A0x,A0y,A0z,A0w);
                        *reinterpret_cast<float4*>(d+4) =make_float4(A1x,A1y,A1z,A1w);
                        *reinterpret_cast<float4*>(d+8) =make_float4(A2x,A2y,A2z,A2w);
                        *reinterpret_cast<float4*>(d+12)=make_float4(A3x,A3y,A3z,A3w);
                    }
                } else if(warp==9){
                    float s=0.f;
#pragma unroll
                    for(int j=0;j<8;++j) s+=red[lane+32*j];
#pragma unroll
                    for(int o=16;o>0;o>>=1) s+=__shfl_down_sync(0xffffffffu,s,o);
                    if(lane==0) sc[4]=s;
                } else if(tid>=320){
                    int a=tid-320;
                    uv[a]=redu[a]+redu[64+a]+redu[128+a]+redu[192+a];
                }
                nbar(2,384);
                // merge half-1 partials (scalar adds)
                for(int e=tid;e<136*16;e+=384){
                    int tile=e>>4, pos=e&15;
                    int ti=0; while((ti+1)*(ti+2)/2<=tile) ++ti;
                    int tj=tile-ti*(ti+1)/2;
                    B3[(4*ti+(pos>>2))*MSM+4*tj+(pos&3)]+=B7[e];
                }
                nbar(2,384);
                // P5: mirror Wm; Wfull both triangles
                for(int e=tid;e<Kn*Kn;e+=384){
                    int a=e>>6,b=e&63;
                    if(b>a) continue;
                    float wm=B3[a*MSM+b];
                    float wf=wm;
                    for(int j=0;j<nm;++j){
                        int ich=midx[j];
                        wf+=dinv[ich]*Ls[ich*MSL+a]*Ls[ich*MSL+b];
                    }
                    B3[b*MSM+a]=wm;
                    B5[a*MSM+b]=wf; B5[b*MSM+a]=wf;
                }
                nbar(2,384);
                // prefetch Lambda(t+1), obs(t+1): Ls dead
                if(t+1<Tn){
                    const float* Lg=Lam+(size_t)(t+1)*Nn*Kn;
                    unsigned base=s2u(Ls);
                    for(int e4=tid;e4<(Nn*Kn)/4;e4+=384){
                        int i=e4>>4,c=(e4&15)<<2;
                        cpa16(base+(unsigned)(i*MSL+c)*4u, Lg+e4*4);
                    }
                    if(tid<64) cpa16(s2u(obs_s)+(unsigned)tid*16u, obs+(size_t)(t+1)*Nn+tid*4);
                }
                cpa_commit();
            } else {
                chol_grp(B1,invdv,0,384,640,3);
            }
            __syncthreads();
        } else {
            // -------- fallback (non-uniform R): sequential --------
            if(tid<528){
                int a0=2*s_ti,a1=a0+1,b0=2*s_tj,b1=b0+1;
                float m00=0,m01=0,m10=0,m11=0,q00=0,q01=0,q10=0,q11=0;
#pragma unroll 2
                for(int i=0;i<Nn;++i){
                    float cm=wmv[i], c2=w2v[i];
                    float la0=Ls[i*MSL+a0], la1=Ls[i*MSL+a1];
                    float lb0=Ls[i*MSL+b0], lb1=Ls[i*MSL+b1];
                    float p00=la0*lb0,p01=la0*lb1,p10=la1*lb0,p11=la1*lb1;
                    m00+=cm*p00;m01+=cm*p01;m10+=cm*p10;m11+=cm*p11;
                    q00+=c2*p00;q01+=c2*p01;q10+=c2*p10;q11+=c2*p11;
                }
                B3[a0*MSM+b0]=m00;B3[a0*MSM+b1]=m01;B3[a1*MSM+b0]=m10;B3[a1*MSM+b1]=m11;
                B7[a0*MSM+b0]=q00;B7[a0*MSM+b1]=q01;B7[a1*MSM+b0]=q10;B7[a1*MSM+b1]=q11;
            } else if(warp==17){
                float s=0.f;
#pragma unroll
                for(int j=0;j<8;++j) s+=red[lane+32*j];
#pragma unroll
                for(int o=16;o>0;o>>=1) s+=__shfl_down_sync(0xffffffffu,s,o);
                if(lane==0) sc[4]=s;
            } else if(tid>=576 && tid<640){
                int a=tid-576;
                uv[a]=redu[a]+redu[64+a]+redu[128+a]+redu[192+a];
            }
            __syncthreads();
            for(int e=tid;e<Kn*Kn;e+=NT){
                int a=e>>6,b=e&63;
                if(b>a) continue;
                float wm=B3[a*MSM+b];
                float wr=wm-1e-4f*B7[a*MSM+b];
                float wf=wm;
                for(int j=0;j<nm;++j){
                    int ich=midx[j];
                    wf+=dinv[ich]*Ls[ich*MSL+a]*Ls[ich*MSL+b];
                }
                B3[b*MSM+a]=wm;
                B7[a*MSM+b]=wr; B7[b*MSM+a]=wr;
                B5[a*MSM+b]=wf; B5[b*MSM+a]=wf;
            }
            __syncthreads();
            if(t+1<Tn){
                const float* Lg=Lam+(size_t)(t+1)*Nn*Kn;
                unsigned base=s2u(Ls);
#pragma unroll
                for(int r=0;r<4;++r){
                    int e4=tid+r*NT;
                    int i=e4>>4,c=(e4&15)<<2;
                    cpa16(base+(unsigned)(i*MSL+c)*4u, Lg+e4*4);
                }
                if(tid<64) cpa16(s2u(obs_s)+(unsigned)tid*16u, obs+(size_t)(t+1)*Nn+tid*4);
            }
            cpa_commit();
            chol_grp(B1,invdv,0,0,NT,3);
            __syncthreads();
        }

        // P7: WG = Wfull*G (triangular-aware)
        g_nn_lowY(tid,B6,B5,B1);
        __syncthreads();

        // P8: Y+I = G^T*WG + I, lower only (G upper zero -> k from a0)
        if(tid<528){
            int a0=2*s_ti,a1=a0+1,b0=2*s_tj,b1=b0+1;
            float c00=0,c01=0,c10=0,c11=0;
            for(int k=a0;k<Kn;++k){
                float x0=B1[k*MSM+a0], x1=B1[k*MSM+a1];
                float y0=B6[k*MSM+b0], y1=B6[k*MSM+b1];
                c00+=x0*y0;c01+=x0*y1;c10+=x1*y0;c11+=x1*y1;
            }
            if(a0==b0)c00+=1.f; if(a0==b1)c01+=1.f; if(a1==b0)c10+=1.f; if(a1==b1)c11+=1.f;
            B4[a0*MSM+b0]=c00;B4[a0*MSM+b1]=c01;B4[a1*MSM+b0]=c10;B4[a1*MSM+b1]=c11;
        }
        __syncthreads();

        // P9: H = chol(Y+I); logdetP+logdetM -> sc[5]
        chol_grp(B4,invdv,&sc[5],0,NT,3);

        // P10: 16x16 diag-block inverses of H (tids 0..63)
        if(tid<64){
            int p=tid>>4, cc=tid&15;
            const float* D=&B4[(p*16)*MSM+p*16];
            float col[16];
#pragma unroll
            for(int i=0;i<16;++i){
                if(i<cc) col[i]=0.f;
                else{
                    float s=(i==cc)?1.f:0.f;
#pragma unroll
                    for(int k=0;k<16;++k) if(k>=cc&&k<i) s-=D[i*MSM+k]*col[k];
                    col[i]=s*invdv[p*16+i];
                }
            }
#pragma unroll
            for(int i=0;i<16;++i) invD[p*272+i*17+cc]=col[i];
        }
        __syncthreads();

        // P11: E (B5) via blocked trsm E H^T = G  (warp-local rows)
#pragma unroll 1
        for(int jb=0;jb<4;++jb){
            int j0=jb*16;
            {
                int r=tid>>4, c=tid&15;
                float s=B1[r*MSM+j0+c];
                for(int k=0;k<j0;++k) s-=B5[r*MSM+k]*B4[(j0+c)*MSM+k];
                redu[r*16+c]=s;
            }
            __syncwarp();
            {
                int r=tid>>4, cc=tid&15;
                float s=0.f;
#pragma unroll
                for(int c=0;c<16;++c) if(c<=cc) s+=redu[r*16+c]*invD[jb*272+cc*17+c];
                B5[r*MSM+j0+cc]=s;
            }
            __syncwarp();
        }
        __syncthreads();

        // P12: Minv = E*E^T, lower + inline mirror -> B6
        if(tid<528){
            int a0=2*s_ti,a1=a0+1,b0=2*s_tj,b1=b0+1;
            float c00=0,c01=0,c10=0,c11=0;
#pragma unroll 8
            for(int k=0;k<Kn;++k){
                float x0=B5[a0*MSM+k],x1=B5[a1*MSM+k];
                float y0=B5[b0*MSM+k],y1=B5[b1*MSM+k];
                c00+=x0*y0;c01+=x0*y1;c10+=x1*y0;c11+=x1*y1;
            }
            B6[a0*MSM+b0]=c00;B6[a0*MSM+b1]=c01;B6[a1*MSM+b0]=c10;B6[a1*MSM+b1]=c11;
            B6[b0*MSM+a0]=c00;B6[b1*MSM+a0]=c01;B6[b0*MSM+a1]=c10;B6[b1*MSM+a1]=c11;
        }
        __syncthreads();

        // P14: KGL = Minv*Wm -> B4 ; x = Minv*u (tid<64)
        g_nn(tid,B4,B6,B3);
        if(tid<Kn){
            float s=0.f;
#pragma unroll 8
            for(int k=0;k<Kn;++k) s+=B6[tid*MSM+k]*uv[k];
            xv[tid]=s;
        }
        __syncthreads();

        // P15: KGRKG -> B3 (lower+mirror) ; quad (warp 17)
        if(unifR){
            if(tid<528){
                int a0=2*s_ti,a1=a0+1,b0=2*s_tj,b1=b0+1;
                float c00=0,c01=0,c10=0,c11=0;
#pragma unroll 8
                for(int k=0;k<Kn;++k){
                    float x0=B4[a0*MSM+k],x1=B4[a1*MSM+k];
                    float y0=B6[k*MSM+b0],y1=B6[k*MSM+b1];
                    c00+=x0*y0;c01+=x0*y1;c10+=x1*y0;c11+=x1*y1;
                }
                c00*=crS;c01*=crS;c10*=crS;c11*=crS;
                B3[a0*MSM+b0]=c00;B3[a0*MSM+b1]=c01;B3[a1*MSM+b0]=c10;B3[a1*MSM+b1]=c11;
                B3[b0*MSM+a0]=c00;B3[b1*MSM+a0]=c01;B3[b0*MSM+a1]=c10;B3[b1*MSM+a1]=c11;
            } else if(warp==17){
                int e=lane*2;
                float p=uv[e]*xv[e]+uv[e+1]*xv[e+1];
#pragma unroll
                for(int o=16;o>0;o>>=1) p+=__shfl_down_sync(0xffffffffu,p,o);
                if(lane==0) sc[7]=p;
            }
            __syncthreads();
        } else {
            // Ttmp = Minv*Wr -> B3 temp (Wm in B3 is dead after P14)
            g_nn(tid,B3,B6,B7);
            __syncthreads();
            // KGRKG = Ttmp*Minv -> B7, then copy to B3
            if(tid<528){
                int a0=2*s_ti,a1=a0+1,b0=2*s_tj,b1=b0+1;
                float c00=0,c01=0,c10=0,c11=0;
#pragma unroll 8
                for(int k=0;k<Kn;++k){
                    float x0=B3[a0*MSM+k],x1=B3[a1*MSM+k];
                    float y0=B6[k*MSM+b0],y1=B6[k*MSM+b1];
                    c00+=x0*y0;c01+=x0*y1;c10+=x1*y0;c11+=x1*y1;
                }
                B7[a0*MSM+b0]=c00;B7[a0*MSM+b1]=c01;B7[a1*MSM+b0]=c10;B7[a1*MSM+b1]=c11;
                B7[b0*MSM+a0]=c00;B7[b1*MSM+a0]=c01;B7[b0*MSM+a1]=c10;B7[b1*MSM+a1]=c11;
            } else if(warp==17){
                int e=lane*2;
                float p=uv[e]*xv[e]+uv[e+1]*xv[e+1];
#pragma unroll
                for(int o=16;o>0;o>>=1) p+=__shfl_down_sync(0xffffffffu,p,o);
                if(lane==0) sc[7]=p;
            }
            __syncthreads();
            for(int e=tid;e<Kn*Kn;e+=NT) B3[(e>>6)*MSM+(e&63)]=B7[(e>>6)*MSM+(e&63)];
            __syncthreads();
        }

        // P16: T2 = Ppred - KGL*Ppred -> B5
        g_nn_rsub(tid,B5,B4,B2);
        __syncthreads();

        // P17: Pm = T2 + KGRKG - T2*KGL^T (lower + mirror); outputs
        if(tid<528){
            int a0=2*s_ti,a1=a0+1,b0=2*s_tj,b1=b0+1;
            float c00=0,c01=0,c10=0,c11=0;
#pragma unroll 8
            for(int k=0;k<Kn;++k){
                float x0=B5[a0*MSM+k],x1=B5[a1*MSM+k];
                float y0=B4[b0*MSM+k],y1=B4[b1*MSM+k];
                c00+=x0*y0;c01+=x0*y1;c10+=x1*y0;c11+=x1*y1;
            }
            float v00=B5[a0*MSM+b0]+B3[a0*MSM+b0]-c00;
            float v01=B5[a0*MSM+b1]+B3[a0*MSM+b1]-c01;
            float v10=B5[a1*MSM+b0]+B3[a1*MSM+b0]-c10;
            float v11=B5[a1*MSM+b1]+B3[a1*MSM+b1]-c11;
            Pm[a0*MSM+b0]=v00;Pm[a0*MSM+b1]=v01;Pm[a1*MSM+b0]=v10;Pm[a1*MSM+b1]=v11;
            Pm[b0*MSM+a0]=v00;Pm[b1*MSM+a0]=v01;Pm[b0*MSM+a1]=v10;Pm[b1*MSM+a1]=v11;
        } else if(tid>=544 && tid<608){
            int i=tid-544;
            float z=zpv[i]+xv[i];
            zv[i]=z;
            out[(size_t)t*(Kn+1)+i]=z;
        } else if(tid==608){
            float mahal=sc[4]-sc[7];
            float ll=-0.5f*(sc[3]*LOG2PI_F+ldD+sc[5]+mahal);
            if(!(ll==ll)) ll=-1e6f;
            out[(size_t)t*(Kn+1)+Kn]=ll;
        }
        __syncthreads();
    }
}

extern "C" void kernel_launch(void* const* d_in, const int* in_sizes, int n_in,
                              void* d_out, int out_size)
{
    const float* obs =(const float*)d_in[0];
    const float* Lam =(const float*)d_in[1];
    const float* Araw=(const float*)d_in[2];
    const float* lQ  =(const float*)d_in[3];
    const float* lR  =(const float*)d_in[4];
    float* out=(float*)d_out;

    cudaFuncSetAttribute(kf_kernel, cudaFuncAttributeMaxDynamicSharedMemorySize,
                         SMEM_BYTES);
    kf_kernel<<<1, NT, SMEM_BYTES>>>(obs, Lam, Araw, lQ, lR, out);
}

// round 14
// speedup vs baseline: 3.8212x; 1.1451x over previous
#include <cuda_runtime.h>
#include <math.h>

#define NT 1024
#define PRE_NT 256
#define Tn 2048
#define Nn 256
#define Kn 64
#define MSM 65          // smem matrix row stride (odd -> conflict-free; scalar access)
#define KK 4096         // 64*64 (global W storage stride)
#define WSZ (Kn*MSM)    // 4160
#define LOG2PI_F 1.8378770664093453f

// main-kernel smem floats:
// 6 mats + W double-buffer (2x3) + invD + invdv + redu + cv + scb + vecs + sc/sint
#define SMEM_FLOATS (6*WSZ + 6*WSZ + 4*272 + 64 + 1024 + 128 + 8 + 5*Kn + 16 + 16)
#define SMEM_BYTES (SMEM_FLOATS*4)

#define PRE_SMEM_FLOATS (Nn*Kn + 6*Nn)
#define PRE_SMEM_BYTES (PRE_SMEM_FLOATS*4)

// Precomputed state-independent per-step quantities
__device__ __align__(16) float gWm[(size_t)Tn*KK];   // Lambda^T diag(m/d) Lambda
__device__ __align__(16) float gWf[(size_t)Tn*KK];   // Lambda^T diag(1/d) Lambda
__device__ __align__(16) float gWr[(size_t)Tn*KK];   // Wm - 1e-4 * Lambda^T diag(m/d^2) Lambda
__device__ __align__(16) float gC[(size_t)Tn*Kn];    // Lambda^T (m*y/d)
__device__ __align__(16) float gSc[(size_t)Tn*2];    // alpha, activeN
__device__ float gAm[Kn*Kn];                          // scaled A (general fallback)

static __device__ __forceinline__ unsigned s2u(const void* p){
    unsigned a;
    asm("{ .reg .u64 t; cvta.to.shared.u64 t, %1; cvt.u32.u64 %0, t; }":"=r"(a):"l"(p));
    return a;
}
static __device__ __forceinline__ void cpa4(unsigned sa, const void* ga){
    asm volatile("cp.async.ca.shared.global [%0], [%1], 4;"::"r"(sa),"l"(ga));
}
static __device__ __forceinline__ void cpa8(unsigned sa, const void* ga){
    asm volatile("cp.async.ca.shared.global [%0], [%1], 8;"::"r"(sa),"l"(ga));
}
static __device__ __forceinline__ void cpa16(unsigned sa, const void* ga){
    asm volatile("cp.async.ca.shared.global [%0], [%1], 16;"::"r"(sa),"l"(ga));
}
static __device__ __forceinline__ void cpa_commit(){ asm volatile("cp.async.commit_group;"); }
static __device__ __forceinline__ void cpa_wait(){ asm volatile("cp.async.wait_group 0;"); }

// ================= precompute kernel: one block per timestep ================
__global__ __launch_bounds__(PRE_NT,2)
void pre_kernel(const float* __restrict__ obs, const float* __restrict__ Lam,
                const float* __restrict__ logR)
{
    extern __shared__ float ps[];
    float* L   = ps;            // [256*64] row stride 64
    float* ys  = L + Nn*Kn;     // [256]
    float* dfv = ys + Nn;
    float* wmv = dfv + Nn;
    float* w2v = wmv + Nn;
    float* wyv = w2v + Nn;
    float* red = wyv + Nn;      // [256]

    const int t = blockIdx.x;
    const int tid = threadIdx.x;

    {   // load Lambda(t) coalesced
        const float4* Lg=(const float4*)(Lam+(size_t)t*Nn*Kn);
        for(int e4=tid;e4<(Nn*Kn)/4;e4+=PRE_NT){
            float4 v=Lg[e4];
            int i=e4>>4,c=(e4&15)<<2;
            *reinterpret_cast<float4*>(&L[i*Kn+c])=v;
        }
    }
    {   // per-channel weights
        float y = obs[(size_t)t*Nn+tid];
        float d = expf(logR[tid])+1e-4f;
        float df = 1.f/d;
        bool nanm = !(y==y);
        ys[tid]  = nanm?0.f:y;
        dfv[tid] = df;
        wmv[tid] = nanm?0.f:df;
        w2v[tid] = nanm?0.f:df*df;
        wyv[tid] = nanm?0.f:y*df;
    }
    __syncthreads();

    // c(t) partials: thread (a, seg)
    {
        int a=tid&63, s=tid>>6;
        float p=0.f;
#pragma unroll 8
        for(int ii=0;ii<64;++ii){
            int i=s*64+ii;
            p+=wyv[i]*L[i*Kn+a];
        }
        red[tid]=p;
    }
    __syncthreads();
    if(tid<Kn)
        gC[(size_t)t*Kn+tid]=red[tid]+red[64+tid]+red[128+tid]+red[192+tid];
    if(tid<32){
        float a1=0.f,n1=0.f;
        for(int i=tid;i<Nn;i+=32){
            a1+=wyv[i]*ys[i];
            n1+=(wmv[i]!=0.f)?1.f:0.f;
        }
#pragma unroll
        for(int o=16;o>0;o>>=1){
            a1+=__shfl_down_sync(0xffffffffu,a1,o);
            n1+=__shfl_down_sync(0xffffffffu,n1,o);
        }
        if(tid==0){ gSc[(size_t)t*2]=a1; gSc[(size_t)t*2+1]=n1; }
    }

    // triple weighted SYRK (lower 2x2 tiles, mirrored on store)
    const size_t base=(size_t)t*KK;
    for(int e=tid;e<528;e+=PRE_NT){
        int ti=0; while((ti+1)*(ti+2)/2<=e) ++ti;
        int tj=e-ti*(ti+1)/2;
        int a0=2*ti,a1i=a0+1,b0=2*tj,b1=b0+1;
        float f00=0,f01=0,f10=0,f11=0;
        float m00=0,m01=0,m10=0,m11=0;
        float q00=0,q01=0,q10=0,q11=0;
#pragma unroll 2
        for(int i=0;i<Nn;++i){
            float la0=L[i*Kn+a0], la1=L[i*Kn+a1i];
            float lb0=L[i*Kn+b0], lb1=L[i*Kn+b1];
            float p00=la0*lb0,p01=la0*lb1,p10=la1*lb0,p11=la1*lb1;
            float df=dfv[i], wm=wmv[i], w2=w2v[i];
            f00+=df*p00; f01+=df*p01; f10+=df*p10; f11+=df*p11;
            m00+=wm*p00; m01+=wm*p01; m10+=wm*p10; m11+=wm*p11;
            q00+=w2*p00; q01+=w2*p01; q10+=w2*p10; q11+=w2*p11;
        }
        float r00=m00-1e-4f*q00, r01=m01-1e-4f*q01;
        float r10=m10-1e-4f*q10, r11=m11-1e-4f*q11;
        gWf[base+a0*Kn+b0]=f00; gWf[base+a0*Kn+b1]=f01;
        gWf[base+a1i*Kn+b0]=f10; gWf[base+a1i*Kn+b1]=f11;
        gWf[base+b0*Kn+a0]=f00; gWf[base+b1*Kn+a0]=f01;
        gWf[base+b0*Kn+a1i]=f10; gWf[base+b1*Kn+a1i]=f11;
        gWm[base+a0*Kn+b0]=m00; gWm[base+a0*Kn+b1]=m01;
        gWm[base+a1i*Kn+b0]=m10; gWm[base+a1i*Kn+b1]=m11;
        gWm[base+b0*Kn+a0]=m00; gWm[base+b1*Kn+a0]=m01;
        gWm[base+b0*Kn+a1i]=m10; gWm[base+b1*Kn+a1i]=m11;
        gWr[base+a0*Kn+b0]=r00; gWr[base+a0*Kn+b1]=r01;
        gWr[base+a1i*Kn+b0]=r10; gWr[base+a1i*Kn+b1]=r11;
        gWr[base+b0*Kn+a0]=r00; gWr[base+b1*Kn+a0]=r01;
        gWr[base+b0*Kn+a1i]=r10; gWr[base+b1*Kn+a1i]=r11;
    }
}

// ============ 64x64 GEMM helpers, 1024 thr, rows 2w,2w+1; cols l,l+32 =======
static __device__ __forceinline__ void g_nn(int tid,float* C,const float* X,const float* Y){
    int w=tid>>5,l=tid&31;
    int a0=w*2,a1=a0+1,b0=l,b1=l+32;
    float c00=0,c01=0,c10=0,c11=0;
#pragma unroll 8
    for(int k=0;k<Kn;++k){
        float x0=X[a0*MSM+k],x1=X[a1*MSM+k];
        float y0=Y[k*MSM+b0],y1=Y[k*MSM+b1];
        c00+=x0*y0;c01+=x0*y1;c10+=x1*y0;c11+=x1*y1;
    }
    C[a0*MSM+b0]=c00;C[a0*MSM+b1]=c01;C[a1*MSM+b0]=c10;C[a1*MSM+b1]=c11;
}
// C = X*G, G lower-triangular: warp w owns cols 2w,2w+1; k >= 2w
static __device__ __forceinline__ void g_nn_lowY(int tid,float* C,const float* X,const float* G){
    int w=tid>>5,l=tid&31;
    int c0=2*w,c1=c0+1;
    float c00=0,c01=0,c10=0,c11=0;
    for(int k=c0;k<Kn;++k){
        float g0=G[k*MSM+c0], g1=G[k*MSM+c1];
        float x0=X[l*MSM+k],  x1=X[(l+32)*MSM+k];
        c00+=x0*g0;c01+=x0*g1;c10+=x1*g0;c11+=x1*g1;
    }
    C[l*MSM+c0]=c00; C[l*MSM+c1]=c01;
    C[(l+32)*MSM+c0]=c10; C[(l+32)*MSM+c1]=c11;
}

// ============ blocked Cholesky, NB=16 (full block, __syncthreads) ===========
static __device__ void chol_blk(float* __restrict__ A, float* __restrict__ invdv,
                                float* __restrict__ logOut)
{
    const int tid=threadIdx.x, lane=tid&31;
    float plog=0.f;
#pragma unroll 1
    for(int p=0;p<4;++p){
        const int j0=p*16;
        if(tid<32){
            float a[16];
#pragma unroll
            for(int i=0;i<16;++i)
                a[i]=(lane<16 && i>=lane)?A[(j0+i)*MSM+j0+lane]:0.f;
            float prod=1.f;
#pragma unroll
            for(int j=0;j<16;++j){
                float dj=__shfl_sync(0xffffffffu,a[j],j);
                float d=sqrtf(dj), inv=1.f/d;
                prod*=d;
                if(lane==j){
                    a[j]=d;
#pragma unroll
                    for(int i=0;i<16;++i) if(i>j) a[i]*=inv;
                    invdv[j0+j]=inv;
                }
                float Lcj=0.f;
#pragma unroll
                for(int i=0;i<16;++i){
                    if(i>j){
                        float Lij=__shfl_sync(0xffffffffu,a[i],j);
                        if(i==lane) Lcj=Lij;
                        if(lane>j && i>=lane) a[i]-=Lij*Lcj;
                    }
                }
            }
            if(lane<16){
#pragma unroll
                for(int i=0;i<16;++i)
                    if(i>=lane) A[(j0+i)*MSM+j0+lane]=a[i];
            }
            if(lane==0) plog+=logf(prod);
        }
        __syncthreads();
        const int rem=48-16*p;
        if(rem>0){
            if(tid<rem){
                const int r=j0+16+tid;
                float x[16];
#pragma unroll
                for(int c=0;c<16;++c) x[c]=A[r*MSM+j0+c];
#pragma unroll
                for(int c=0;c<16;++c){
                    float s=x[c];
#pragma unroll
                    for(int k=0;k<16;++k) if(k<c) s-=x[k]*A[(j0+c)*MSM+j0+k];
                    x[c]=s*invdv[j0+c];
                }
#pragma unroll
                for(int c=0;c<16;++c) A[r*MSM+j0+c]=x[c];
            }
            __syncthreads();
            for(int e=tid;e<rem*rem;e+=NT){
                int i=e/rem, j2=e-i*rem;
                if(j2<=i){
                    int gi=j0+16+i, gj=j0+16+j2;
                    float s=0.f;
#pragma unroll
                    for(int k=0;k<16;++k) s+=A[gi*MSM+j0+k]*A[gj*MSM+j0+k];
                    A[gi*MSM+gj]-=s;
                }
            }
            __syncthreads();
        }
    }
    if(logOut && tid==0) *logOut=2.f*plog;
}

// ===========================================================================
__global__ __launch_bounds__(NT,1)
void kf_kernel(const float* __restrict__ Araw, const float* __restrict__ logQ,
               const float* __restrict__ logR, float* __restrict__ out)
{
    extern __shared__ float sm[];
    float* Pm   = sm;                 // persistent P (full, symmetric)
    float* B1   = Pm + WSZ;           // Ppred-lower -> G -> (Ttmp)
    float* B2   = B1 + WSZ;           // WG -> KGL
    float* B4   = B2 + WSZ;           // Y+I -> H
    float* B5   = B4 + WSZ;           // E -> Z
    float* B6   = B5 + WSZ;           // Minv (and P1 temp)
    float* WB   = B6 + WSZ;           // [2][3][WSZ]  Wm, Wf, Wr double buffered
    float* invD = WB + 6*WSZ;         // [4][16][17]
    float* invdv= invD + 4*272;       // [64]
    float* redu = invdv + 64;         // [1024]
    float* cv   = redu + 1024;        // [2][64]
    float* scb  = cv + 128;           // [2][2]  alpha, actN
    float* zv   = scb + 8;            // vectors
    float* zpv  = zv + Kn;
    float* uv   = zpv + Kn;
    float* xv   = uv + Kn;
    float* qd   = xv + Kn;
    float* sc   = qd + Kn;            // [16]
    int*   sint = (int*)(sc + 16);    // [16]

    const int tid=threadIdx.x, warp=tid>>5, lane=tid&31;

    // ------------------------------- prologue -------------------------------
    for(int e=tid;e<KK;e+=NT) B1[(e>>6)*MSM+(e&63)]=Araw[e];
    if(tid<Kn) qd[tid]=expf(logQ[tid]);
    if(tid==0) sint[1]=1;
    __syncthreads();
    if(tid==0){
        float ld=0.f;
        float d0=expf(logR[0])+1e-4f;
        int u=1;
        for(int i=0;i<Nn;++i){
            float d=expf(logR[i])+1e-4f;
            ld+=logf(d);
            if(d!=d0) u=0;
        }
        sc[0]=ld; sint[2]=u; sc[8]=1.f-1e-4f/d0;
    }
    {   // exact scalar-A detection
        float a00=Araw[0]; int ok=1;
        for(int e=tid;e<KK;e+=NT){
            int r=e>>6,c=e&63; float v=Araw[e];
            if(r==c){ if(v!=a00) ok=0; } else { if(v!=0.f) ok=0; }
        }
        if(!ok) atomicAnd(&sint[1],0);
    }
    // power iteration for sigma_max(A_raw)
    if(tid<Kn) redu[tid]=1.f;
    __syncthreads();
#pragma unroll 1
    for(int it=0;it<64;++it){
        if(tid<Kn){ float s=0.f; for(int k=0;k<Kn;++k) s+=B1[tid*MSM+k]*redu[k]; redu[256+tid]=s; }
        __syncthreads();
        if(tid<Kn){ float s=0.f; for(int k=0;k<Kn;++k) s+=B1[k*MSM+tid]*redu[256+k]; redu[512+tid]=s; }
        __syncthreads();
        if(tid==0){
            float n=0.f; for(int i=0;i<Kn;++i) n+=redu[512+i]*redu[512+i];
            sc[1]=rsqrtf(fmaxf(n,1e-30f));
        }
        __syncthreads();
        if(tid<Kn) redu[tid]=redu[512+tid]*sc[1];
        __syncthreads();
    }
    if(tid<Kn){ float s=0.f; for(int k=0;k<Kn;++k) s+=B1[tid*MSM+k]*redu[k]; redu[256+tid]=s; }
    __syncthreads();
    if(tid==0){
        float n=0.f; for(int i=0;i<Kn;++i) n+=redu[256+i]*redu[256+i];
        float sigma=sqrtf(n);
        sc[2]=0.98f/(sigma+1e-6f);
        sc[6]=sc[2]*Araw[0];
    }
    __syncthreads();
    if(!sint[1]){ float s=sc[2]; for(int e=tid;e<KK;e+=NT) gAm[e]=s*Araw[e]; }
    for(int e=tid;e<KK;e+=NT){ int r=e>>6,c=e&63; Pm[r*MSM+c]=(r==c)?1.f:0.f; }
    if(tid<Kn) zv[tid]=0.f;
    __syncthreads();
    const int scA=sint[1], unifR=sint[2];
    const float aA=sc[6], ldD=sc[0], crS=sc[8];

    // lower 2x2 tile map (528 tiles)
    int s_ti=0,s_tj=0;
    if(tid<528){
        int ti=0; while((ti+1)*(ti+2)/2<=tid) ++ti;
        s_ti=ti; s_tj=tid-ti*(ti+1)/2;
    }

    // prefetch t=0 into buffer 0
    {
        size_t base=0;
        unsigned d0=s2u(WB), d1=s2u(WB+WSZ), d2=s2u(WB+2*WSZ);
#pragma unroll
        for(int r2=0;r2<4;++r2){
            int e=tid+r2*NT;
            int row=e>>6,c=e&63;
            unsigned off=(unsigned)(row*MSM+c)*4u;
            cpa4(d0+off, gWm+base+e);
            cpa4(d1+off, gWf+base+e);
            cpa4(d2+off, gWr+base+e);
        }
        if(tid<16) cpa16(s2u(cv)+(unsigned)tid*16u, gC+tid*4);
        else if(tid==16) cpa8(s2u(scb), gSc);
        cpa_commit();
    }

    // ------------------------------- main loop ------------------------------
#pragma unroll 1
    for(int t=0;t<Tn;++t){
        const int b=t&1;
        float* WmB=WB+b*3*WSZ;
        float* WfB=WmB+WSZ;
        float* WrB=WfB+WSZ;
        float* cvB=cv+b*64;
        float* scB=scb+b*2;

        cpa_wait();
        __syncthreads();

        // P1: B1 = lower(Ppred) (upper zero); zpv
        if(scA){
            float a2=aA*aA;
            for(int e=tid;e<KK;e+=NT){
                int a=e>>6,c=e&63;
                float v;
                if(c<=a){ v=a2*Pm[a*MSM+c]; if(a==c) v+=qd[a]; }
                else v=0.f;
                B1[a*MSM+c]=v;
            }
            if(tid<Kn) zpv[tid]=aA*zv[tid];
            __syncthreads();
        } else {
            for(int e=tid;e<KK;e+=NT) B6[(e>>6)*MSM+(e&63)]=gAm[e];
            __syncthreads();
            g_nn(tid,B5,B6,Pm);                       // B5 = A*P
            if(tid<Kn){ float s=0.f; for(int k=0;k<Kn;++k) s+=B6[tid*MSM+k]*zv[k]; zpv[tid]=s; }
            __syncthreads();
            if(tid<528){                               // B1 lower = (A P) A^T + Q
                int a0=2*s_ti,a1=a0+1,b0=2*s_tj,b1=b0+1;
                float c00=0,c01=0,c10=0,c11=0;
#pragma unroll 8
                for(int k=0;k<Kn;++k){
                    float x0=B5[a0*MSM+k],x1=B5[a1*MSM+k];
                    float y0=B6[b0*MSM+k],y1=B6[b1*MSM+k];
                    c00+=x0*y0;c01+=x0*y1;c10+=x1*y0;c11+=x1*y1;
                }
                if(a0==b0)c00+=qd[a0];
                if(a1==b1&&b1<=a1)c11+=qd[a1];
                B1[a0*MSM+b0]=c00;
                if(b1<=a0) B1[a0*MSM+b1]=c01;
                B1[a1*MSM+b0]=c10;
                if(b1<=a1) B1[a1*MSM+b1]=c11;
            } else {
                for(int e=tid-528;e<KK;e+=(NT-528)){
                    int a=e>>6,c=e&63;
                    if(c>a) B1[a*MSM+c]=0.f;
                }
            }
            __syncthreads();
        }

        // issue prefetch for t+1
        if(t+1<Tn){
            const int nb=(t+1)&1;
            size_t base=(size_t)(t+1)*KK;
            float* W0=WB+nb*3*WSZ;
            unsigned d0=s2u(W0), d1=s2u(W0+WSZ), d2=s2u(W0+2*WSZ);
#pragma unroll
            for(int r2=0;r2<4;++r2){
                int e=tid+r2*NT;
                int row=e>>6,c=e&63;
                unsigned off=(unsigned)(row*MSM+c)*4u;
                cpa4(d0+off, gWm+base+e);
                cpa4(d1+off, gWf+base+e);
                cpa4(d2+off, gWr+base+e);
            }
            if(tid<16) cpa16(s2u(cv+nb*64)+(unsigned)tid*16u, gC+(size_t)(t+1)*Kn+tid*4);
            else if(tid==16) cpa8(s2u(scb+nb*2), gSc+(size_t)(t+1)*2);
        }
        cpa_commit();

        // P2: G = chol(Ppred)
        chol_blk(B1,invdv,0);

        // P3: WG = Wf * G (triangular-aware)
        g_nn_lowY(tid,B2,WfB,B1);
        __syncthreads();

        // P4: Y+I lower (528) || u-partials (640..895)
        if(tid<528){
            int a0=2*s_ti,a1=a0+1,b0=2*s_tj,b1=b0+1;
            float c00=0,c01=0,c10=0,c11=0;
            for(int k=a0;k<Kn;++k){
                float x0=B1[k*MSM+a0], x1=B1[k*MSM+a1];
                float y0=B2[k*MSM+b0], y1=B2[k*MSM+b1];
                c00+=x0*y0;c01+=x0*y1;c10+=x1*y0;c11+=x1*y1;
            }
            if(a0==b0)c00+=1.f; if(a0==b1)c01+=1.f;
            if(a1==b0)c10+=1.f; if(a1==b1)c11+=1.f;
            B4[a0*MSM+b0]=c00;B4[a0*MSM+b1]=c01;
            B4[a1*MSM+b0]=c10;B4[a1*MSM+b1]=c11;
        } else if(tid>=640 && tid<896){
            int e=tid-640, r=e&63, s=e>>6;
            float p=0.f;
#pragma unroll
            for(int kk=0;kk<16;++kk){
                int k=s*16+kk;
                p+=WmB[k*MSM+r]*zpv[k];
            }
            redu[s*64+r]=p;
        }
        __syncthreads();

        // P5: H = chol(Y+I); logdetP+logdetM -> sc[5]
        chol_blk(B4,invdv,&sc[5]);

        // P6: invD (0..63) || uv finalize (64..127)
        if(tid<64){
            int p=tid>>4, cc=tid&15;
            const float* D=&B4[(p*16)*MSM+p*16];
            float col[16];
#pragma unroll
            for(int i=0;i<16;++i){
                if(i<cc) col[i]=0.f;
                else{
                    float s=(i==cc)?1.f:0.f;
#pragma unroll
                    for(int k=0;k<16;++k) if(k>=cc&&k<i) s-=D[i*MSM+k]*col[k];
                    col[i]=s*invdv[p*16+i];
                }
            }
#pragma unroll
            for(int i=0;i<16;++i) invD[p*272+i*17+cc]=col[i];
        } else if(tid<128){
            int r=tid-64;
            uv[r]=cvB[r]-(redu[r]+redu[64+r]+redu[128+r]+redu[192+r]);
        }
        __syncthreads();

        // P7: E = G H^{-T} via blocked trsm (warp-local rows)
#pragma unroll 1
        for(int jb=0;jb<4;++jb){
            int j0=jb*16;
            {
                int r=tid>>4, c=tid&15;
                float s=B1[r*MSM+j0+c];
                for(int k=0;k<j0;++k) s-=B5[r*MSM+k]*B4[(j0+c)*MSM+k];
                redu[r*16+c]=s;
            }
            __syncwarp();
            {
                int r=tid>>4, cc=tid&15;
                float s=0.f;
#pragma unroll
                for(int c=0;c<16;++c) if(c<=cc) s+=redu[r*16+c]*invD[jb*272+cc*17+c];
                B5[r*MSM+j0+cc]=s;
            }
            __syncwarp();
        }
        __syncthreads();

        // P8: Minv = E E^T lower+mirror (528) || x=E(E^T u),quad (warp17) || sdv (warp18)
        if(tid<528){
            int a0=2*s_ti,a1=a0+1,b0=2*s_tj,b1=b0+1;
            float c00=0,c01=0,c10=0,c11=0;
#pragma unroll 8
            for(int k=0;k<Kn;++k){
                float x0=B5[a0*MSM+k],x1=B5[a1*MSM+k];
                float y0=B5[b0*MSM+k],y1=B5[b1*MSM+k];
                c00+=x0*y0;c01+=x0*y1;c10+=x1*y0;c11+=x1*y1;
            }
            B6[a0*MSM+b0]=c00;B6[a0*MSM+b1]=c01;B6[a1*MSM+b0]=c10;B6[a1*MSM+b1]=c11;
            B6[b0*MSM+a0]=c00;B6[b1*MSM+a0]=c01;B6[b0*MSM+a1]=c10;B6[b1*MSM+a1]=c11;
        } else if(warp==17){
            int r0=2*lane, r1=r0+1;
            float t0=0.f,t1=0.f;
            for(int k=0;k<Kn;++k){
                float u=uv[k];
                t0+=B5[k*MSM+r0]*u;
                t1+=B5[k*MSM+r1]*u;
            }
            redu[512+r0]=t0; redu[512+r1]=t1;
            __syncwarp();
            float x0=0.f,x1=0.f;
            for(int k=0;k<Kn;++k){
                float w=redu[512+k];
                x0+=B5[r0*MSM+k]*w;
                x1+=B5[r1*MSM+k]*w;
            }
            xv[r0]=x0; xv[r1]=x1;
            float q=uv[r0]*x0+uv[r1]*x1;
#pragma unroll
            for(int o=16;o>0;o>>=1) q+=__shfl_down_sync(0xffffffffu,q,o);
            if(lane==0) sc[7]=q;
        } else if(warp==18){
            int e0=2*lane, e1=e0+1;
            float p=zpv[e0]*(cvB[e0]+uv[e0])+zpv[e1]*(cvB[e1]+uv[e1]);
#pragma unroll
            for(int o=16;o>0;o>>=1) p+=__shfl_down_sync(0xffffffffu,p,o);
            if(lane==0){ sc[4]=scB[0]-p; sc[3]=scB[1]; }
        }
        __syncthreads();

        // P9: KGL = Minv * Wm -> B2
        g_nn(tid,B2,B6,WmB);
        __syncthreads();

        // P10: Z = (I - KGL) * G -> B5 (overwrites E; tri-aware k>=c0)
        {
            int w=tid>>5,l=tid&31;
            int c0=2*w,c1=c0+1;
            int r0=l, r1=l+32;
            float z00=0,z01=0,z10=0,z11=0;
            for(int k=c0;k<Kn;++k){
                float g0=B1[k*MSM+c0], g1=B1[k*MSM+c1];
                float x0=B2[r0*MSM+k], x1=B2[r1*MSM+k];
                z00+=x0*g0;z01+=x0*g1;z10+=x1*g0;z11+=x1*g1;
            }
            float g00=(r0>=c0)?B1[r0*MSM+c0]:0.f;
            float g01=(r0>=c1)?B1[r0*MSM+c1]:0.f;
            float g10=(r1>=c0)?B1[r1*MSM+c0]:0.f;
            float g11=(r1>=c1)?B1[r1*MSM+c1]:0.f;
            B5[r0*MSM+c0]=g00-z00; B5[r0*MSM+c1]=g01-z01;
            B5[r1*MSM+c0]=g10-z10; B5[r1*MSM+c1]=g11-z11;
        }
        __syncthreads();

        // P10b (non-uniform R): Ttmp = Minv * Wr -> B1 (G dead)
        const float* XX; float ss;
        if(unifR){ XX=B2; ss=crS; }
        else {
            g_nn(tid,B1,B6,WrB);
            __syncthreads();
            XX=B1; ss=1.f;
        }

        // P11: Pm = Z Z^T + ss * XX * Minv (lower+mirror) || outputs
        if(tid<528){
            int a0=2*s_ti,a1=a0+1,b0=2*s_tj,b1=b0+1;
            float c00=0,c01=0,c10=0,c11=0;
            float w00=0,w01=0,w10=0,w11=0;
#pragma unroll 4
            for(int k=0;k<Kn;++k){
                float za0=B5[a0*MSM+k],za1=B5[a1*MSM+k];
                float zb0=B5[b0*MSM+k],zb1=B5[b1*MSM+k];
                c00+=za0*zb0;c01+=za0*zb1;c10+=za1*zb0;c11+=za1*zb1;
                float xa0=XX[a0*MSM+k],xa1=XX[a1*MSM+k];
                float mb0=B6[k*MSM+b0],mb1=B6[k*MSM+b1];
                w00+=xa0*mb0;w01+=xa0*mb1;w10+=xa1*mb0;w11+=xa1*mb1;
            }
            float v00=c00+ss*w00, v01=c01+ss*w01;
            float v10=c10+ss*w10, v11=c11+ss*w11;
            Pm[a0*MSM+b0]=v00;Pm[a0*MSM+b1]=v01;Pm[a1*MSM+b0]=v10;Pm[a1*MSM+b1]=v11;
            Pm[b0*MSM+a0]=v00;Pm[b1*MSM+a0]=v01;Pm[b0*MSM+a1]=v10;Pm[b1*MSM+a1]=v11;
        } else if(tid>=544 && tid<608){
            int i=tid-544;
            float z=zpv[i]+xv[i];
            zv[i]=z;
            out[(size_t)t*(Kn+1)+i]=z;
        } else if(tid==608){
            float mahal=sc[4]-sc[7];
            float ll=-0.5f*(sc[3]*LOG2PI_F+ldD+sc[5]+mahal);
            if(!(ll==ll)) ll=-1e6f;
            out[(size_t)t*(Kn+1)+Kn]=ll;
        }
        __syncthreads();
    }
}

extern "C" void kernel_launch(void* const* d_in, const int* in_sizes, int n_in,
                              void* d_out, int out_size)
{
    const float* obs =(const float*)d_in[0];
    const float* Lam =(const float*)d_in[1];
    const float* Araw=(const float*)d_in[2];
    const float* lQ  =(const float*)d_in[3];
    const float* lR  =(const float*)d_in[4];
    float* out=(float*)d_out;

    cudaFuncSetAttribute(pre_kernel, cudaFuncAttributeMaxDynamicSharedMemorySize,
                         PRE_SMEM_BYTES);
    cudaFuncSetAttribute(kf_kernel, cudaFuncAttributeMaxDynamicSharedMemorySize,
                         SMEM_BYTES);
    pre_kernel<<<Tn, PRE_NT, PRE_SMEM_BYTES>>>(obs, Lam, lR);
    kf_kernel<<<1, NT, SMEM_BYTES>>>(Araw, lQ, lR, out);
}

// round 16
// speedup vs baseline: 4.0064x; 1.0485x over previous
#include <cuda_runtime.h>
#include <math.h>

#define NT 512
#define PRE_NT 256
#define Tn 2048
#define Nn 256
#define Kn 64
#define MSM 65          // smem matrix row stride (odd -> conflict-free; scalar access)
#define KK 4096
#define WSZ (Kn*MSM)
#define LOG2PI_F 1.8378770664093453f

#define SMEM_FLOATS (6*WSZ + 6*WSZ + 4*272 + 64 + 1024 + 128 + 8 + 5*Kn + 16 + 16)
#define SMEM_BYTES (SMEM_FLOATS*4)

#define PRE_SMEM_FLOATS (Nn*Kn + 6*Nn)
#define PRE_SMEM_BYTES (PRE_SMEM_FLOATS*4)

// Precomputed state-independent per-step quantities
__device__ __align__(16) float gWm[(size_t)Tn*KK];
__device__ __align__(16) float gWf[(size_t)Tn*KK];
__device__ __align__(16) float gWr[(size_t)Tn*KK];
__device__ __align__(16) float gC[(size_t)Tn*Kn];
__device__ __align__(16) float gSc[(size_t)Tn*2];
__device__ float gAm[Kn*Kn];

static __device__ __forceinline__ unsigned s2u(const void* p){
    unsigned a;
    asm("{ .reg .u64 t; cvta.to.shared.u64 t, %1; cvt.u32.u64 %0, t; }":"=r"(a):"l"(p));
    return a;
}
static __device__ __forceinline__ void cpa4(unsigned sa, const void* ga){
    asm volatile("cp.async.ca.shared.global [%0], [%1], 4;"::"r"(sa),"l"(ga));
}
static __device__ __forceinline__ void cpa8(unsigned sa, const void* ga){
    asm volatile("cp.async.ca.shared.global [%0], [%1], 8;"::"r"(sa),"l"(ga));
}
static __device__ __forceinline__ void cpa16(unsigned sa, const void* ga){
    asm volatile("cp.async.ca.shared.global [%0], [%1], 16;"::"r"(sa),"l"(ga));
}
static __device__ __forceinline__ void cpa_commit(){ asm volatile("cp.async.commit_group;"); }
static __device__ __forceinline__ void cpa_wait(){ asm volatile("cp.async.wait_group 0;"); }
static __device__ __forceinline__ void nbar(int id, int cnt){
    asm volatile("bar.sync %0, %1;" :: "r"(id), "r"(cnt) : "memory");
}

// ================= precompute kernel (unchanged, passing) ===================
__global__ __launch_bounds__(PRE_NT,2)
void pre_kernel(const float* __restrict__ obs, const float* __restrict__ Lam,
                const float* __restrict__ logR)
{
    extern __shared__ float ps[];
    float* L   = ps;
    float* ys  = L + Nn*Kn;
    float* dfv = ys + Nn;
    float* wmv = dfv + Nn;
    float* w2v = wmv + Nn;
    float* wyv = w2v + Nn;
    float* red = wyv + Nn;

    const int t = blockIdx.x;
    const int tid = threadIdx.x;

    {
        const float4* Lg=(const float4*)(Lam+(size_t)t*Nn*Kn);
        for(int e4=tid;e4<(Nn*Kn)/4;e4+=PRE_NT){
            float4 v=Lg[e4];
            int i=e4>>4,c=(e4&15)<<2;
            *reinterpret_cast<float4*>(&L[i*Kn+c])=v;
        }
    }
    {
        float y = obs[(size_t)t*Nn+tid];
        float d = expf(logR[tid])+1e-4f;
        float df = 1.f/d;
        bool nanm = !(y==y);
        ys[tid]  = nanm?0.f:y;
        dfv[tid] = df;
        wmv[tid] = nanm?0.f:df;
        w2v[tid] = nanm?0.f:df*df;
        wyv[tid] = nanm?0.f:y*df;
    }
    __syncthreads();
    {
        int a=tid&63, s=tid>>6;
        float p=0.f;
#pragma unroll 8
        for(int ii=0;ii<64;++ii){
            int i=s*64+ii;
            p+=wyv[i]*L[i*Kn+a];
        }
        red[tid]=p;
    }
    __syncthreads();
    if(tid<Kn)
        gC[(size_t)t*Kn+tid]=red[tid]+red[64+tid]+red[128+tid]+red[192+tid];
    if(tid<32){
        float a1=0.f,n1=0.f;
        for(int i=tid;i<Nn;i+=32){
            a1+=wyv[i]*ys[i];
            n1+=(wmv[i]!=0.f)?1.f:0.f;
        }
#pragma unroll
        for(int o=16;o>0;o>>=1){
            a1+=__shfl_down_sync(0xffffffffu,a1,o);
            n1+=__shfl_down_sync(0xffffffffu,n1,o);
        }
        if(tid==0){ gSc[(size_t)t*2]=a1; gSc[(size_t)t*2+1]=n1; }
    }
    const size_t base=(size_t)t*KK;
    for(int e=tid;e<528;e+=PRE_NT){
        int ti=0; while((ti+1)*(ti+2)/2<=e) ++ti;
        int tj=e-ti*(ti+1)/2;
        int a0=2*ti,a1i=a0+1,b0=2*tj,b1=b0+1;
        float f00=0,f01=0,f10=0,f11=0;
        float m00=0,m01=0,m10=0,m11=0;
        float q00=0,q01=0,q10=0,q11=0;
#pragma unroll 2
        for(int i=0;i<Nn;++i){
            float la0=L[i*Kn+a0], la1=L[i*Kn+a1i];
            float lb0=L[i*Kn+b0], lb1=L[i*Kn+b1];
            float p00=la0*lb0,p01=la0*lb1,p10=la1*lb0,p11=la1*lb1;
            float df=dfv[i], wm=wmv[i], w2=w2v[i];
            f00+=df*p00; f01+=df*p01; f10+=df*p10; f11+=df*p11;
            m00+=wm*p00; m01+=wm*p01; m10+=wm*p10; m11+=wm*p11;
            q00+=w2*p00; q01+=w2*p01; q10+=w2*p10; q11+=w2*p11;
        }
        float r00=m00-1e-4f*q00, r01=m01-1e-4f*q01;
        float r10=m10-1e-4f*q10, r11=m11-1e-4f*q11;
        gWf[base+a0*Kn+b0]=f00; gWf[base+a0*Kn+b1]=f01;
        gWf[base+a1i*Kn+b0]=f10; gWf[base+a1i*Kn+b1]=f11;
        gWf[base+b0*Kn+a0]=f00; gWf[base+b1*Kn+a0]=f01;
        gWf[base+b0*Kn+a1i]=f10; gWf[base+b1*Kn+a1i]=f11;
        gWm[base+a0*Kn+b0]=m00; gWm[base+a0*Kn+b1]=m01;
        gWm[base+a1i*Kn+b0]=m10; gWm[base+a1i*Kn+b1]=m11;
        gWm[base+b0*Kn+a0]=m00; gWm[base+b1*Kn+a0]=m01;
        gWm[base+b0*Kn+a1i]=m10; gWm[base+b1*Kn+a1i]=m11;
        gWr[base+a0*Kn+b0]=r00; gWr[base+a0*Kn+b1]=r01;
        gWr[base+a1i*Kn+b0]=r10; gWr[base+a1i*Kn+b1]=r11;
        gWr[base+b0*Kn+a0]=r00; gWr[base+b1*Kn+a0]=r01;
        gWr[base+b0*Kn+a1i]=r10; gWr[base+b1*Kn+a1i]=r11;
    }
}

// ========== full 64x64 GEMM, 512 thr, 2 rows x 4 cols per thread ============
static __device__ __forceinline__ void g_nn512(int tid,float* C,const float* X,const float* Y){
    const int a0=2*(tid>>4), a1=a0+1, b=tid&15;
    float c00=0,c01=0,c02=0,c03=0,c10=0,c11=0,c12=0,c13=0;
#pragma unroll 8
    for(int k=0;k<Kn;++k){
        float x0=X[a0*MSM+k], x1=X[a1*MSM+k];
        float y0=Y[k*MSM+b], y1=Y[k*MSM+b+16], y2=Y[k*MSM+b+32], y3=Y[k*MSM+b+48];
        c00+=x0*y0;c01+=x0*y1;c02+=x0*y2;c03+=x0*y3;
        c10+=x1*y0;c11+=x1*y1;c12+=x1*y2;c13+=x1*y3;
    }
    C[a0*MSM+b]=c00;C[a0*MSM+b+16]=c01;C[a0*MSM+b+32]=c02;C[a0*MSM+b+48]=c03;
    C[a1*MSM+b]=c10;C[a1*MSM+b+16]=c11;C[a1*MSM+b+32]=c12;C[a1*MSM+b+48]=c13;
}

// ============ blocked Cholesky, NB=16, group-parameterized ==================
static __device__ void chol_grp(float* __restrict__ A, float* __restrict__ invdv,
                                float* __restrict__ logOut,
                                int cnt, int barid)
{
    const int tg=(int)threadIdx.x, lane=tg&31;
    float plog=0.f;
#pragma unroll 1
    for(int p=0;p<4;++p){
        const int j0=p*16;
        if(tg<32){
            float a[16];
#pragma unroll
            for(int i=0;i<16;++i)
                a[i]=(lane<16 && i>=lane)?A[(j0+i)*MSM+j0+lane]:0.f;
            float prod=1.f;
#pragma unroll
            for(int j=0;j<16;++j){
                float dj=__shfl_sync(0xffffffffu,a[j],j);
                float d=sqrtf(dj), inv=1.f/d;
                prod*=d;
                if(lane==j){
                    a[j]=d;
#pragma unroll
                    for(int i=0;i<16;++i) if(i>j) a[i]*=inv;
                    invdv[j0+j]=inv;
                }
                float Lcj=0.f;
#pragma unroll
                for(int i=0;i<16;++i){
                    if(i>j){
                        float Lij=__shfl_sync(0xffffffffu,a[i],j);
                        if(i==lane) Lcj=Lij;
                        if(lane>j && i>=lane) a[i]-=Lij*Lcj;
                    }
                }
            }
            if(lane<16){
#pragma unroll
                for(int i=0;i<16;++i)
                    if(i>=lane) A[(j0+i)*MSM+j0+lane]=a[i];
            }
            if(lane==0) plog+=logf(prod);
        }
        nbar(barid,cnt);
        const int rem=48-16*p;
        if(rem>0){
            if(tg<rem){
                const int r=j0+16+tg;
                float x[16];
#pragma unroll
                for(int c=0;c<16;++c) x[c]=A[r*MSM+j0+c];
#pragma unroll
                for(int c=0;c<16;++c){
                    float s=x[c];
#pragma unroll
                    for(int k=0;k<16;++k) if(k<c) s-=x[k]*A[(j0+c)*MSM+j0+k];
                    x[c]=s*invdv[j0+c];
                }
#pragma unroll
                for(int c=0;c<16;++c) A[r*MSM+j0+c]=x[c];
            }
            nbar(barid,cnt);
            for(int e=tg;e<rem*rem;e+=cnt){
                int i=e/rem, j2=e-i*rem;
                if(j2<=i){
                    int gi=j0+16+i, gj=j0+16+j2;
                    float s=0.f;
#pragma unroll
                    for(int k=0;k<16;++k) s+=A[gi*MSM+j0+k]*A[gj*MSM+j0+k];
                    A[gi*MSM+gj]-=s;
                }
            }
            nbar(barid,cnt);
        }
    }
    if(logOut && tg==0) *logOut=2.f*plog;
}

// ===========================================================================
__global__ __launch_bounds__(NT,1)
void kf_kernel(const float* __restrict__ Araw, const float* __restrict__ logQ,
               const float* __restrict__ logR, float* __restrict__ out)
{
    extern __shared__ float sm[];
    float* Pm   = sm;
    float* B1   = Pm + WSZ;           // Ppred-lower -> G -> (Ttmp)
    float* B2   = B1 + WSZ;           // WG -> KGL
    float* B4   = B2 + WSZ;           // Y+I -> H
    float* B5   = B4 + WSZ;           // E -> Z
    float* B6   = B5 + WSZ;           // Minv / P1-temp
    float* WB   = B6 + WSZ;           // [2][3][WSZ]
    float* invD = WB + 6*WSZ;
    float* invdv= invD + 4*272;
    float* redu = invdv + 64;         // [1024]
    float* cv   = redu + 1024;        // [2][64]
    float* scb  = cv + 128;           // [2][2]
    float* zv   = scb + 8;
    float* zpv  = zv + Kn;
    float* uv   = zpv + Kn;
    float* xv   = uv + Kn;
    float* qd   = xv + Kn;
    float* sc   = qd + Kn;            // [16]
    int*   sint = (int*)(sc + 16);

    const int tid=threadIdx.x;

    // ------------------------------- prologue -------------------------------
    for(int e=tid;e<KK;e+=NT) B1[(e>>6)*MSM+(e&63)]=Araw[e];
    if(tid<Kn) qd[tid]=expf(logQ[tid]);
    if(tid==0) sint[1]=1;
    __syncthreads();
    if(tid==0){
        float ld=0.f;
        float d0=expf(logR[0])+1e-4f;
        int u=1;
        for(int i=0;i<Nn;++i){
            float d=expf(logR[i])+1e-4f;
            ld+=logf(d);
            if(d!=d0) u=0;
        }
        sc[0]=ld; sint[2]=u; sc[8]=1.f-1e-4f/d0;
    }
    {
        float a00=Araw[0]; int ok=1;
        for(int e=tid;e<KK;e+=NT){
            int r=e>>6,c=e&63; float v=Araw[e];
            if(r==c){ if(v!=a00) ok=0; } else { if(v!=0.f) ok=0; }
        }
        if(!ok) atomicAnd(&sint[1],0);
    }
    if(tid<Kn) redu[tid]=1.f;
    __syncthreads();
#pragma unroll 1
    for(int it=0;it<64;++it){
        if(tid<Kn){ float s=0.f; for(int k=0;k<Kn;++k) s+=B1[tid*MSM+k]*redu[k]; redu[256+tid]=s; }
        __syncthreads();
        if(tid<Kn){ float s=0.f; for(int k=0;k<Kn;++k) s+=B1[k*MSM+tid]*redu[256+k]; redu[512+tid]=s; }
        __syncthreads();
        if(tid==0){
            float n=0.f; for(int i=0;i<Kn;++i) n+=redu[512+i]*redu[512+i];
            sc[1]=rsqrtf(fmaxf(n,1e-30f));
        }
        __syncthreads();
        if(tid<Kn) redu[tid]=redu[512+tid]*sc[1];
        __syncthreads();
    }
    if(tid<Kn){ float s=0.f; for(int k=0;k<Kn;++k) s+=B1[tid*MSM+k]*redu[k]; redu[256+tid]=s; }
    __syncthreads();
    if(tid==0){
        float n=0.f; for(int i=0;i<Kn;++i) n+=redu[256+i]*redu[256+i];
        float sigma=sqrtf(n);
        sc[2]=0.98f/(sigma+1e-6f);
        sc[6]=sc[2]*Araw[0];
    }
    __syncthreads();
    if(!sint[1]){ float s=sc[2]; for(int e=tid;e<KK;e+=NT) gAm[e]=s*Araw[e]; }
    for(int e=tid;e<KK;e+=NT){ int r=e>>6,c=e&63; Pm[r*MSM+c]=(r==c)?1.f:0.f; }
    if(tid<Kn) zv[tid]=0.f;
    __syncthreads();
    const int scA=sint[1], unifR=sint[2];
    const float aA=sc[6], ldD=sc[0], crS=sc[8];

    // lower 2x4 tile map (272 tiles): rows 2ti..2ti+1, cols 4tj..4tj+3
    int s_ti=0,s_tj=0;
    if(tid<272){
        int cum=0, ti=0;
        while(cum + ((ti>>1)+1) <= tid){ cum += (ti>>1)+1; ++ti; }
        s_ti=ti; s_tj=tid-cum;
    }

    // prefetch t=0
    {
        unsigned d0=s2u(WB), d1=s2u(WB+WSZ), d2=s2u(WB+2*WSZ);
#pragma unroll
        for(int r2=0;r2<8;++r2){
            int e=tid+r2*NT;
            int row=e>>6,c=e&63;
            unsigned off=(unsigned)(row*MSM+c)*4u;
            cpa4(d0+off, gWm+e);
            cpa4(d1+off, gWf+e);
            cpa4(d2+off, gWr+e);
        }
        if(tid<16) cpa16(s2u(cv)+(unsigned)tid*16u, gC+tid*4);
        else if(tid==16) cpa8(s2u(scb), gSc);
        cpa_commit();
    }

    // ------------------------------- main loop ------------------------------
#pragma unroll 1
    for(int t=0;t<Tn;++t){
        const int b=t&1;
        float* WmB=WB+b*3*WSZ;
        float* WfB=WmB+WSZ;
        float* WrB=WfB+WSZ;
        float* cvB=cv+b*64;
        float* scB=scb+b*2;

        cpa_wait();
        __syncthreads();

        // P1: B1 = lower(Ppred), upper zero; zpv
        if(scA){
            float a2=aA*aA;
            for(int e=tid;e<KK;e+=NT){
                int a=e>>6,c=e&63;
                float v;
                if(c<=a){ v=a2*Pm[a*MSM+c]; if(a==c) v+=qd[a]; }
                else v=0.f;
                B1[a*MSM+c]=v;
            }
            if(tid<Kn) zpv[tid]=aA*zv[tid];
            __syncthreads();
        } else {
            for(int e=tid;e<KK;e+=NT) B6[(e>>6)*MSM+(e&63)]=gAm[e];
            __syncthreads();
            g_nn512(tid,B5,B6,Pm);                 // B5 = A*P
            if(tid<Kn){ float s=0.f; for(int k=0;k<Kn;++k) s+=B6[tid*MSM+k]*zv[k]; zpv[tid]=s; }
            __syncthreads();
            if(tid<272){                            // B1 lower = (AP)A^T + Q
                int a0=2*s_ti,a1=a0+1,b0=4*s_tj;
#pragma unroll
                for(int i=0;i<2;++i){
                    int a=a0+i;
#pragma unroll
                    for(int j=0;j<4;++j){
                        int c=b0+j;
                        if(c>a) continue;
                        float s=0.f;
#pragma unroll 8
                        for(int k=0;k<Kn;++k) s+=B5[a*MSM+k]*B6[c*MSM+k];
                        if(a==c) s+=qd[a];
                        B1[a*MSM+c]=s;
                    }
                }
            } else {
                for(int e=tid-272;e<KK;e+=(NT-272)){
                    int a=e>>6,c=e&63;
                    if(c>a) B1[a*MSM+c]=0.f;
                }
            }
            __syncthreads();
        }

        // prefetch t+1
        if(t+1<Tn){
            const int nb=(t+1)&1;
            size_t base=(size_t)(t+1)*KK;
            float* W0=WB+nb*3*WSZ;
            unsigned d0=s2u(W0), d1=s2u(W0+WSZ), d2=s2u(W0+2*WSZ);
#pragma unroll
            for(int r2=0;r2<8;++r2){
                int e=tid+r2*NT;
                int row=e>>6,c=e&63;
                unsigned off=(unsigned)(row*MSM+c)*4u;
                cpa4(d0+off, gWm+base+e);
                cpa4(d1+off, gWf+base+e);
                cpa4(d2+off, gWr+base+e);
            }
            if(tid<16) cpa16(s2u(cv+nb*64)+(unsigned)tid*16u, gC+(size_t)(t+1)*Kn+tid*4);
            else if(tid==16) cpa8(s2u(scb+nb*2), gSc+(size_t)(t+1)*2);
        }
        cpa_commit();

        // P2: chol(G) [0..383] || u-partials Wm*zpv [384..511]
        if(tid<384){
            chol_grp(B1,invdv,0,384,3);
        } else {
            int e=tid-384, r=e&63, s=e>>6;     // 2 segments of 32 k
            float p=0.f;
#pragma unroll 8
            for(int kk=0;kk<32;++kk){
                int k=32*s+kk;
                p+=WmB[r*MSM+k]*zpv[k];
            }
            redu[s*64+r]=p;
        }
        __syncthreads();

        // P3: WG = Wf * G (full GEMM; G upper zero)
        g_nn512(tid,B2,WfB,B1);
        __syncthreads();

        // P4: Y+I lower tiles [0..271] || uv finalize [272..335]
        if(tid<272){
            int a0=2*s_ti,a1=a0+1,b0=4*s_tj;
            float c0[4]={0,0,0,0}, c1[4]={0,0,0,0};
            for(int k=a0;k<Kn;++k){
                float x0=B1[k*MSM+a0], x1=B1[k*MSM+a1];
                float y0=B2[k*MSM+b0], y1=B2[k*MSM+b0+1];
                float y2=B2[k*MSM+b0+2], y3=B2[k*MSM+b0+3];
                c0[0]+=x0*y0;c0[1]+=x0*y1;c0[2]+=x0*y2;c0[3]+=x0*y3;
                c1[0]+=x1*y0;c1[1]+=x1*y1;c1[2]+=x1*y2;c1[3]+=x1*y3;
            }
#pragma unroll
            for(int j=0;j<4;++j){
                int cc=b0+j;
                if(a0==cc) c0[j]+=1.f;
                if(a1==cc) c1[j]+=1.f;
                B4[a0*MSM+cc]=c0[j];
                B4[a1*MSM+cc]=c1[j];
            }
        } else if(tid<336){
            int r=tid-272;
            uv[r]=cvB[r]-(redu[r]+redu[64+r]);
        }
        __syncthreads();

        // P5: H = chol(Y+I) [0..383] || sdv [384..415]
        if(tid<384){
            chol_grp(B4,invdv,&sc[5],384,3);
        } else if(tid<416){
            int lane=tid-384;
            int e0=2*lane, e1=e0+1;
            float p=zpv[e0]*(cvB[e0]+uv[e0])+zpv[e1]*(cvB[e1]+uv[e1]);
#pragma unroll
            for(int o=16;o>0;o>>=1) p+=__shfl_down_sync(0xffffffffu,p,o);
            if(lane==0){ sc[4]=scB[0]-p; sc[3]=scB[1]; }
        }
        __syncthreads();

        // P6: 16x16 diag-block inverses of H (tids 0..63)
        if(tid<64){
            int p=tid>>4, cc=tid&15;
            const float* D=&B4[(p*16)*MSM+p*16];
            float col[16];
#pragma unroll
            for(int i=0;i<16;++i){
                if(i<cc) col[i]=0.f;
                else{
                    float s=(i==cc)?1.f:0.f;
#pragma unroll
                    for(int k=0;k<16;++k) if(k>=cc&&k<i) s-=D[i*MSM+k]*col[k];
                    col[i]=s*invdv[p*16+i];
                }
            }
#pragma unroll
            for(int i=0;i<16;++i) invD[p*272+i*17+cc]=col[i];
        }
        __syncthreads();

        // P7: E = G H^{-T} blocked trsm, 2 rows/thread, warp-local
#pragma unroll 1
        for(int jb=0;jb<4;++jb){
            int j0=jb*16;
            int r=tid>>4, c=tid&15;
            int r2=r+32;
            {
                float s1=B1[r*MSM+j0+c], s2=B1[r2*MSM+j0+c];
                for(int k=0;k<j0;++k){
                    float h=B4[(j0+c)*MSM+k];
                    s1-=B5[r*MSM+k]*h;
                    s2-=B5[r2*MSM+k]*h;
                }
                redu[r*16+c]=s1; redu[r2*16+c]=s2;
            }
            __syncwarp();
            {
                float o1=0.f,o2=0.f;
#pragma unroll
                for(int c2=0;c2<16;++c2) if(c2<=c){
                    float d=invD[jb*272+c*17+c2];
                    o1+=redu[r*16+c2]*d;
                    o2+=redu[r2*16+c2]*d;
                }
                B5[r*MSM+j0+c]=o1; B5[r2*MSM+j0+c]=o2;
            }
            __syncwarp();
        }
        __syncthreads();

        // P8: Minv = E E^T lower+mirror [0..271] || w=E^T u, x=E w, quad [288..351]
        if(tid<272){
            int a0=2*s_ti,a1=a0+1,b0=4*s_tj;
            float c0[4]={0,0,0,0}, c1[4]={0,0,0,0};
#pragma unroll 4
            for(int k=0;k<Kn;++k){
                float x0=B5[a0*MSM+k], x1=B5[a1*MSM+k];
                float y0=B5[b0*MSM+k], y1=B5[(b0+1)*MSM+k];
                float y2=B5[(b0+2)*MSM+k], y3=B5[(b0+3)*MSM+k];
                c0[0]+=x0*y0;c0[1]+=x0*y1;c0[2]+=x0*y2;c0[3]+=x0*y3;
                c1[0]+=x1*y0;c1[1]+=x1*y1;c1[2]+=x1*y2;c1[3]+=x1*y3;
            }
#pragma unroll
            for(int j=0;j<4;++j){
                int cc=b0+j;
                if(cc<=a0){ B6[a0*MSM+cc]=c0[j]; B6[cc*MSM+a0]=c0[j]; }
                if(cc<=a1){ B6[a1*MSM+cc]=c1[j]; B6[cc*MSM+a1]=c1[j]; }
            }
        } else if(tid>=288 && tid<352){
            int r=tid-288;
            float w=0.f;
            for(int k=0;k<Kn;++k) w+=B5[k*MSM+r]*uv[k];
            redu[512+r]=w;
            float q=w*w;
#pragma unroll
            for(int o=16;o>0;o>>=1) q+=__shfl_down_sync(0xffffffffu,q,o);
            if((r&31)==0) redu[640+(r>>5)]=q;
            nbar(4,64);
            float x=0.f;
            for(int k=0;k<Kn;++k) x+=B5[r*MSM+k]*redu[512+k];
            xv[r]=x;
            if(r==0) sc[7]=redu[640]+redu[641];
        }
        __syncthreads();

        // P9: KGL = Minv * Wm
        g_nn512(tid,B2,B6,WmB);
        __syncthreads();

        // P10: Z = G - KGL*G -> B5
        {
            const int a0=2*(tid>>4), a1=a0+1, bb=tid&15;
            float c00=0,c01=0,c02=0,c03=0,c10=0,c11=0,c12=0,c13=0;
#pragma unroll 8
            for(int k=0;k<Kn;++k){
                float x0=B2[a0*MSM+k], x1=B2[a1*MSM+k];
                float y0=B1[k*MSM+bb], y1=B1[k*MSM+bb+16], y2=B1[k*MSM+bb+32], y3=B1[k*MSM+bb+48];
                c00+=x0*y0;c01+=x0*y1;c02+=x0*y2;c03+=x0*y3;
                c10+=x1*y0;c11+=x1*y1;c12+=x1*y2;c13+=x1*y3;
            }
            B5[a0*MSM+bb]   =B1[a0*MSM+bb]   -c00;
            B5[a0*MSM+bb+16]=B1[a0*MSM+bb+16]-c01;
            B5[a0*MSM+bb+32]=B1[a0*MSM+bb+32]-c02;
            B5[a0*MSM+bb+48]=B1[a0*MSM+bb+48]-c03;
            B5[a1*MSM+bb]   =B1[a1*MSM+bb]   -c10;
            B5[a1*MSM+bb+16]=B1[a1*MSM+bb+16]-c11;
            B5[a1*MSM+bb+32]=B1[a1*MSM+bb+32]-c12;
            B5[a1*MSM+bb+48]=B1[a1*MSM+bb+48]-c13;
        }
        __syncthreads();

        // P10b (non-uniform R): Ttmp = Minv*Wr -> B1 (G dead)
        const float* XX; float ss;
        if(unifR){ XX=B2; ss=crS; }
        else {
            g_nn512(tid,B1,B6,WrB);
            __syncthreads();
            XX=B1; ss=1.f;
        }

        // P11: Pm = Z Z^T + ss * XX * Minv (lower+mirror) [0..271] || outputs
        if(tid<272){
            int a0=2*s_ti,a1=a0+1,b0=4*s_tj;
            float c0[4]={0,0,0,0}, c1[4]={0,0,0,0};
#pragma unroll 2
            for(int k=0;k<Kn;++k){
                float za0=B5[a0*MSM+k], za1=B5[a1*MSM+k];
                float zb0=B5[b0*MSM+k], zb1=B5[(b0+1)*MSM+k];
                float zb2=B5[(b0+2)*MSM+k], zb3=B5[(b0+3)*MSM+k];
                c0[0]+=za0*zb0;c0[1]+=za0*zb1;c0[2]+=za0*zb2;c0[3]+=za0*zb3;
                c1[0]+=za1*zb0;c1[1]+=za1*zb1;c1[2]+=za1*zb2;c1[3]+=za1*zb3;
                float xa0=ss*XX[a0*MSM+k], xa1=ss*XX[a1*MSM+k];
                float mb0=B6[b0*MSM+k], mb1=B6[(b0+1)*MSM+k];
                float mb2=B6[(b0+2)*MSM+k], mb3=B6[(b0+3)*MSM+k];
                c0[0]+=xa0*mb0;c0[1]+=xa0*mb1;c0[2]+=xa0*mb2;c0[3]+=xa0*mb3;
                c1[0]+=xa1*mb0;c1[1]+=xa1*mb1;c1[2]+=xa1*mb2;c1[3]+=xa1*mb3;
            }
#pragma unroll
            for(int j=0;j<4;++j){
                int cc=b0+j;
                if(cc<=a0){ Pm[a0*MSM+cc]=c0[j]; Pm[cc*MSM+a0]=c0[j]; }
                if(cc<=a1){ Pm[a1*MSM+cc]=c1[j]; Pm[cc*MSM+a1]=c1[j]; }
            }
        } else if(tid>=272 && tid<336){
            int i=tid-272;
            float z=zpv[i]+xv[i];
            zv[i]=z;
            out[(size_t)t*(Kn+1)+i]=z;
        } else if(tid==336){
            float mahal=sc[4]-sc[7];
            float ll=-0.5f*(sc[3]*LOG2PI_F+ldD+sc[5]+mahal);
            if(!(ll==ll)) ll=-1e6f;
            out[(size_t)t*(Kn+1)+Kn]=ll;
        }
        __syncthreads();
    }
}

extern "C" void kernel_launch(void* const* d_in, const int* in_sizes, int n_in,
                              void* d_out, int out_size)
{
    const float* obs =(const float*)d_in[0];
    const float* Lam =(const float*)d_in[1];
    const float* Araw=(const float*)d_in[2];
    const float* lQ  =(const float*)d_in[3];
    const float* lR  =(const float*)d_in[4];
    float* out=(float*)d_out;

    cudaFuncSetAttribute(pre_kernel, cudaFuncAttributeMaxDynamicSharedMemorySize,
                         PRE_SMEM_BYTES);
    cudaFuncSetAttribute(kf_kernel, cudaFuncAttributeMaxDynamicSharedMemorySize,
                         SMEM_BYTES);
    pre_kernel<<<Tn, PRE_NT, PRE_SMEM_BYTES>>>(obs, Lam, lR);
    kf_kernel<<<1, NT, SMEM_BYTES>>>(Araw, lQ, lR, out);
}